// round 1
// baseline (speedup 1.0000x reference)
#include <cuda_runtime.h>
#include <cuda_bf16.h>
#include <math.h>
#include <stdint.h>

// ---------------- problem constants ----------------
constexpr int NN   = 20000;    // nodes
constexpr int EE   = 320000;   // edges (before doubling)
constexpr int E2   = 2 * EE;   // doubled edges
constexpr int FIN  = 256;
constexpr int FE   = 32;
constexpr int HID  = 128;
constexpr int HEADS = 4;
constexpr int D1   = HEADS * HID; // 512

// ---------------- device scratch (static, no allocs) ----------------
__device__ float g_h1   [(size_t)NN * D1];   // x@W1
__device__ float g_out1 [(size_t)NN * D1];   // layer1 output (post ELU)
__device__ float g_h2t  [(size_t)NN * HID];  // h@W2
__device__ float g_h2   [(size_t)NN * HID];  // layer2 output (post ELU)
__device__ float g_z    [(size_t)NN * HID];  // proj1 output (post PReLU)
__device__ float g_s1   [NN * HEADS];
__device__ float g_d1   [NN * HEADS];
__device__ float g_s2   [NN];
__device__ float g_d2   [NN];
__device__ float g_aep1 [(size_t)EE * HEADS];
__device__ float g_aep2 [EE];
__device__ float g_wev1 [FE * HEADS];
__device__ float g_wev2 [FE];
__device__ int   g_deg  [NN];
__device__ int   g_rowptr[NN + 1];
__device__ int   g_cursor[NN];
__device__ int   g_csrc [E2];
__device__ int   g_ceid [E2];
__device__ float g_colsum[HID];

// ---------------- small helpers ----------------
__global__ void zero_k() {
    int i = blockIdx.x * blockDim.x + threadIdx.x;
    if (i < NN) g_deg[i] = 0;
    if (i < HID) g_colsum[i] = 0.f;
}

// wev1[f*4+h] = sum_c We1[f,h*128+c]*ae1[h,c];  wev2[f] = sum_c We2[f,c]*ae2[c]
__global__ void wev_k(const float* __restrict__ We1, const float* __restrict__ ae1,
                      const float* __restrict__ We2, const float* __restrict__ ae2) {
    int t = threadIdx.x;
    if (t < FE * HEADS) {
        int f = t >> 2, h = t & 3;
        float s = 0.f;
        for (int c = 0; c < HID; c++) s += We1[(size_t)f * D1 + h * HID + c] * ae1[h * HID + c];
        g_wev1[t] = s;
    } else if (t < FE * HEADS + FE) {
        int f = t - FE * HEADS;
        float s = 0.f;
        for (int c = 0; c < HID; c++) s += We2[(size_t)f * HID + c] * ae2[c];
        g_wev2[f] = s;
    }
}

// per-edge logit contributions: aep1[e,h] = ea[e,:] . wev1[:,h]; aep2[e] = ea[e,:] . wev2
__global__ __launch_bounds__(256) void aeproj_k(const float* __restrict__ ea) {
    __shared__ float w1s[FE * HEADS];
    __shared__ float w2s[FE];
    int tid = threadIdx.x;
    if (tid < FE * HEADS) w1s[tid] = g_wev1[tid];
    if (tid < FE)         w2s[tid] = g_wev2[tid];
    __syncthreads();
    int e = blockIdx.x * 8 + (tid >> 5);
    int lane = tid & 31;
    if (e >= EE) return;
    float v = ea[(size_t)e * FE + lane];
    float p0 = v * w1s[lane * 4 + 0];
    float p1 = v * w1s[lane * 4 + 1];
    float p2 = v * w1s[lane * 4 + 2];
    float p3 = v * w1s[lane * 4 + 3];
    float p4 = v * w2s[lane];
    #pragma unroll
    for (int off = 16; off > 0; off >>= 1) {
        p0 += __shfl_down_sync(0xffffffffu, p0, off);
        p1 += __shfl_down_sync(0xffffffffu, p1, off);
        p2 += __shfl_down_sync(0xffffffffu, p2, off);
        p3 += __shfl_down_sync(0xffffffffu, p3, off);
        p4 += __shfl_down_sync(0xffffffffu, p4, off);
    }
    if (lane == 0) {
        g_aep1[(size_t)e * 4 + 0] = p0;
        g_aep1[(size_t)e * 4 + 1] = p1;
        g_aep1[(size_t)e * 4 + 2] = p2;
        g_aep1[(size_t)e * 4 + 3] = p3;
        g_aep2[e] = p4;
    }
}

// ---------------- CSR build (by destination) ----------------
__global__ void hist_k(const int* __restrict__ ei) {
    int j = blockIdx.x * blockDim.x + threadIdx.x;
    if (j >= E2) return;
    int dst = (j < EE) ? ei[EE + j] : ei[j - EE];
    atomicAdd(&g_deg[dst], 1);
}

__global__ __launch_bounds__(1024) void scan_k() {
    __shared__ int part[1024];
    int tid = threadIdx.x;
    const int CH = (NN + 1023) / 1024;
    int base = tid * CH;
    int s = 0;
    for (int i = 0; i < CH; i++) {
        int idx = base + i;
        if (idx < NN) s += g_deg[idx];
    }
    part[tid] = s;
    __syncthreads();
    for (int off = 1; off < 1024; off <<= 1) {
        int v = (tid >= off) ? part[tid - off] : 0;
        __syncthreads();
        part[tid] += v;
        __syncthreads();
    }
    int pre = part[tid] - s; // exclusive prefix
    for (int i = 0; i < CH; i++) {
        int idx = base + i;
        if (idx < NN) {
            g_rowptr[idx] = pre;
            g_cursor[idx] = pre;
            pre += g_deg[idx];
        }
    }
    if (tid == 1023) g_rowptr[NN] = part[1023];
}

__global__ void fill_k(const int* __restrict__ ei) {
    int j = blockIdx.x * blockDim.x + threadIdx.x;
    if (j >= E2) return;
    int srcv, dstv, eid;
    if (j < EE) { srcv = ei[j];       dstv = ei[EE + j]; eid = j; }
    else        { int e = j - EE; srcv = ei[EE + e]; dstv = ei[e]; eid = e; }
    int pos = atomicAdd(&g_cursor[dstv], 1);
    g_csrc[pos] = srcv;
    g_ceid[pos] = eid;
}

// ---------------- SGEMM 128x128x8, 256 thr, 8x8 microtile ----------------
// epi: 0 = none, 2 = bias + PReLU(pa[0]), 3 = bias only
__global__ __launch_bounds__(256) void sgemm_k(int M, int N, int K,
        const float* __restrict__ A, const float* __restrict__ B, float* __restrict__ C,
        const float* __restrict__ bias, const float* __restrict__ pa, int epi) {
    __shared__ float As[8][128];
    __shared__ float Bs[8][128];
    int tid = threadIdx.x;
    int rowBase = blockIdx.y * 128;
    int colBase = blockIdx.x * 128;
    int aRow = tid >> 1;
    int aCol = (tid & 1) * 4;
    int bRow = tid >> 5;
    int bCol = (tid & 31) * 4;
    int ty = tid >> 4, tx = tid & 15;
    float acc[8][8];
    #pragma unroll
    for (int i = 0; i < 8; i++)
        #pragma unroll
        for (int j = 0; j < 8; j++) acc[i][j] = 0.f;

    for (int k0 = 0; k0 < K; k0 += 8) {
        float4 av = make_float4(0.f, 0.f, 0.f, 0.f);
        int gr = rowBase + aRow;
        if (gr < M) av = *reinterpret_cast<const float4*>(&A[(size_t)gr * K + k0 + aCol]);
        As[aCol + 0][aRow] = av.x;
        As[aCol + 1][aRow] = av.y;
        As[aCol + 2][aRow] = av.z;
        As[aCol + 3][aRow] = av.w;
        float4 bv = *reinterpret_cast<const float4*>(&B[(size_t)(k0 + bRow) * N + colBase + bCol]);
        *reinterpret_cast<float4*>(&Bs[bRow][bCol]) = bv;
        __syncthreads();
        #pragma unroll
        for (int kk = 0; kk < 8; kk++) {
            float ar[8], br[8];
            #pragma unroll
            for (int i = 0; i < 8; i++) ar[i] = As[kk][ty * 8 + i];
            #pragma unroll
            for (int j = 0; j < 8; j++) br[j] = Bs[kk][tx * 8 + j];
            #pragma unroll
            for (int i = 0; i < 8; i++)
                #pragma unroll
                for (int j = 0; j < 8; j++) acc[i][j] += ar[i] * br[j];
        }
        __syncthreads();
    }
    float pav = (epi == 2) ? pa[0] : 0.f;
    #pragma unroll
    for (int i = 0; i < 8; i++) {
        int r = rowBase + ty * 8 + i;
        if (r >= M) continue;
        #pragma unroll
        for (int j = 0; j < 8; j++) {
            int c = colBase + tx * 8 + j;
            float v = acc[i][j];
            if (epi) {
                v += bias[c];
                if (epi == 2) v = v > 0.f ? v : pav * v;
            }
            C[(size_t)r * N + c] = v;
        }
    }
}

// ---------------- per-node attention dot products ----------------
template <int H, int C>
__global__ void sdot_k(const float* __restrict__ hv, const float* __restrict__ a_s,
                       const float* __restrict__ a_d, float* __restrict__ so, float* __restrict__ dd_out) {
    int wpb = blockDim.x >> 5;
    int gw = blockIdx.x * wpb + (threadIdx.x >> 5);
    int lane = threadIdx.x & 31;
    if (gw >= NN * H) return;
    int n = gw / H, h = gw % H;
    const float* hp = hv + (size_t)n * H * C + h * C;
    float ss = 0.f, dd = 0.f;
    for (int c = lane; c < C; c += 32) {
        float v = hp[c];
        ss += v * a_s[h * C + c];
        dd += v * a_d[h * C + c];
    }
    #pragma unroll
    for (int off = 16; off > 0; off >>= 1) {
        ss += __shfl_down_sync(0xffffffffu, ss, off);
        dd += __shfl_down_sync(0xffffffffu, dd, off);
    }
    if (lane == 0) { so[gw] = ss; dd_out[gw] = dd; }
}

// ---------------- layer-1 aggregation: online softmax, 4 heads, 512 ch ----------------
__global__ __launch_bounds__(256) void gat_agg1(const float* __restrict__ h1,
        const float* __restrict__ bias, float* __restrict__ out) {
    int n = blockIdx.x, tid = threadIdx.x;
    int lane = tid & 31, wid = tid >> 5;
    int start = g_rowptr[n], end = g_rowptr[n + 1];
    __shared__ float w_sh[256][4];
    __shared__ int   src_sh[256];
    __shared__ float wred[8][4];
    __shared__ float bm[4], bs[4];
    float dl[4];
    #pragma unroll
    for (int h = 0; h < 4; h++) dl[h] = g_d1[n * 4 + h];
    float runm[4], runs[4];
    #pragma unroll
    for (int h = 0; h < 4; h++) { runm[h] = -INFINITY; runs[h] = 0.f; }
    float acc0 = 0.f, acc1 = 0.f;
    int h0 = tid >> 7;          // 0 or 1
    int h1i = 2 + (tid >> 7);   // 2 or 3

    for (int t0 = start; t0 < end; t0 += 256) {
        int cnt = min(256, end - t0);
        float l[4];
        if (tid < cnt) {
            int s = g_csrc[t0 + tid];
            int e = g_ceid[t0 + tid];
            src_sh[tid] = s;
            #pragma unroll
            for (int h = 0; h < 4; h++) {
                float xv = g_s1[s * 4 + h] + dl[h] + g_aep1[(size_t)e * 4 + h];
                l[h] = xv > 0.f ? xv : 0.2f * xv;
            }
        } else {
            #pragma unroll
            for (int h = 0; h < 4; h++) l[h] = -INFINITY;
        }
        // block max per head
        float m[4];
        #pragma unroll
        for (int h = 0; h < 4; h++) m[h] = l[h];
        #pragma unroll
        for (int off = 16; off > 0; off >>= 1) {
            #pragma unroll
            for (int h = 0; h < 4; h++) m[h] = fmaxf(m[h], __shfl_down_sync(0xffffffffu, m[h], off));
        }
        if (lane == 0) {
            #pragma unroll
            for (int h = 0; h < 4; h++) wred[wid][h] = m[h];
        }
        __syncthreads();
        if (tid < 4) {
            float mm = -INFINITY;
            #pragma unroll
            for (int w = 0; w < 8; w++) mm = fmaxf(mm, wred[w][tid]);
            bm[tid] = mm;
        }
        __syncthreads();
        float sc[4];
        #pragma unroll
        for (int h = 0; h < 4; h++) {
            float nm = fmaxf(runm[h], bm[h]);
            sc[h] = __expf(runm[h] - nm);
            runm[h] = nm;
        }
        acc0 *= sc[h0];
        acc1 *= sc[h1i];
        float wv[4];
        #pragma unroll
        for (int h = 0; h < 4; h++) {
            wv[h] = (tid < cnt) ? __expf(l[h] - runm[h]) : 0.f;
            w_sh[tid][h] = wv[h];
        }
        // block sum per head
        float su[4];
        #pragma unroll
        for (int h = 0; h < 4; h++) su[h] = wv[h];
        #pragma unroll
        for (int off = 16; off > 0; off >>= 1) {
            #pragma unroll
            for (int h = 0; h < 4; h++) su[h] += __shfl_down_sync(0xffffffffu, su[h], off);
        }
        if (lane == 0) {
            #pragma unroll
            for (int h = 0; h < 4; h++) wred[wid][h] = su[h];
        }
        __syncthreads();
        if (tid < 4) {
            float t = 0.f;
            #pragma unroll
            for (int w = 0; w < 8; w++) t += wred[w][tid];
            bs[tid] = t;
        }
        __syncthreads();
        #pragma unroll
        for (int h = 0; h < 4; h++) runs[h] = runs[h] * sc[h] + bs[h];
        // accumulate (w_sh + src_sh visible via the syncthreads above)
        for (int e = 0; e < cnt; e++) {
            const float* hp = h1 + (size_t)src_sh[e] * D1;
            acc0 += hp[tid]       * w_sh[e][h0];
            acc1 += hp[tid + 256] * w_sh[e][h1i];
        }
        __syncthreads();
    }
    float i0 = runs[h0]  > 0.f ? 1.f / runs[h0]  : 0.f;
    float i1 = runs[h1i] > 0.f ? 1.f / runs[h1i] : 0.f;
    float v0 = acc0 * i0 + bias[tid];
    float v1 = acc1 * i1 + bias[tid + 256];
    v0 = v0 > 0.f ? v0 : (__expf(v0) - 1.f);
    v1 = v1 > 0.f ? v1 : (__expf(v1) - 1.f);
    out[(size_t)n * D1 + tid]       = v0;
    out[(size_t)n * D1 + 256 + tid] = v1;
}

// ---------------- layer-2 aggregation: 1 head, 128 ch ----------------
__global__ __launch_bounds__(128) void gat_agg2(const float* __restrict__ h2t,
        const float* __restrict__ bias, float* __restrict__ out) {
    int n = blockIdx.x, tid = threadIdx.x;
    int lane = tid & 31, wid = tid >> 5;
    int start = g_rowptr[n], end = g_rowptr[n + 1];
    __shared__ float w_sh[128];
    __shared__ int   src_sh[128];
    __shared__ float wred[4];
    __shared__ float bmv, bsv;
    float dl = g_d2[n];
    float runm = -INFINITY, runs = 0.f, acc = 0.f;

    for (int t0 = start; t0 < end; t0 += 128) {
        int cnt = min(128, end - t0);
        float l;
        if (tid < cnt) {
            int s = g_csrc[t0 + tid];
            int e = g_ceid[t0 + tid];
            src_sh[tid] = s;
            float xv = g_s2[s] + dl + g_aep2[e];
            l = xv > 0.f ? xv : 0.2f * xv;
        } else l = -INFINITY;
        float m = l;
        #pragma unroll
        for (int off = 16; off > 0; off >>= 1) m = fmaxf(m, __shfl_down_sync(0xffffffffu, m, off));
        if (lane == 0) wred[wid] = m;
        __syncthreads();
        if (tid == 0) bmv = fmaxf(fmaxf(wred[0], wred[1]), fmaxf(wred[2], wred[3]));
        __syncthreads();
        float nm = fmaxf(runm, bmv);
        float sc = __expf(runm - nm);
        runm = nm;
        acc *= sc;
        float wv = (tid < cnt) ? __expf(l - nm) : 0.f;
        w_sh[tid] = wv;
        float su = wv;
        #pragma unroll
        for (int off = 16; off > 0; off >>= 1) su += __shfl_down_sync(0xffffffffu, su, off);
        if (lane == 0) wred[wid] = su;
        __syncthreads();
        if (tid == 0) bsv = wred[0] + wred[1] + wred[2] + wred[3];
        __syncthreads();
        runs = runs * sc + bsv;
        for (int e = 0; e < cnt; e++)
            acc += h2t[(size_t)src_sh[e] * HID + tid] * w_sh[e];
        __syncthreads();
    }
    float inv = runs > 0.f ? 1.f / runs : 0.f;
    float v = acc * inv + bias[tid];
    v = v > 0.f ? v : (__expf(v) - 1.f);
    out[(size_t)n * HID + tid] = v;
}

// ---------------- column mean + sigmoid ----------------
__global__ void colsum_k(const float* __restrict__ hp) {
    int col = threadIdx.x;
    float acc = 0.f;
    for (int r = blockIdx.x; r < NN; r += gridDim.x) acc += hp[(size_t)r * HID + col];
    atomicAdd(&g_colsum[col], acc);
}

__global__ void final_k(float* __restrict__ outg) {
    int t = threadIdx.x;
    if (t < HID) {
        float m = g_colsum[t] / (float)NN;
        outg[t] = 1.f / (1.f + __expf(-m));
    }
}

// ---------------- launch ----------------
extern "C" void kernel_launch(void* const* d_in, const int* in_sizes, int n_in,
                              void* d_out, int out_size) {
    const float* x   = (const float*)d_in[0];
    const int*   ei  = (const int*)  d_in[1];
    const float* ea  = (const float*)d_in[2];
    const float* W1  = (const float*)d_in[3];
    const float* We1 = (const float*)d_in[4];
    const float* as1 = (const float*)d_in[5];
    const float* ad1 = (const float*)d_in[6];
    const float* ae1 = (const float*)d_in[7];
    const float* b1  = (const float*)d_in[8];
    const float* W2  = (const float*)d_in[9];
    const float* We2 = (const float*)d_in[10];
    const float* as2 = (const float*)d_in[11];
    const float* ad2 = (const float*)d_in[12];
    const float* ae2 = (const float*)d_in[13];
    const float* b2  = (const float*)d_in[14];
    const float* P1  = (const float*)d_in[15];
    const float* pb1 = (const float*)d_in[16];
    const float* pa  = (const float*)d_in[17];
    const float* P2  = (const float*)d_in[18];
    const float* pb2 = (const float*)d_in[19];
    float* out = (float*)d_out;

    float *p_h1, *p_out1, *p_h2t, *p_h2, *p_z, *p_s1, *p_d1, *p_s2, *p_d2;
    cudaGetSymbolAddress((void**)&p_h1,   g_h1);
    cudaGetSymbolAddress((void**)&p_out1, g_out1);
    cudaGetSymbolAddress((void**)&p_h2t,  g_h2t);
    cudaGetSymbolAddress((void**)&p_h2,   g_h2);
    cudaGetSymbolAddress((void**)&p_z,    g_z);
    cudaGetSymbolAddress((void**)&p_s1,   g_s1);
    cudaGetSymbolAddress((void**)&p_d1,   g_d1);
    cudaGetSymbolAddress((void**)&p_s2,   g_s2);
    cudaGetSymbolAddress((void**)&p_d2,   g_d2);

    zero_k<<<(NN + 255) / 256, 256>>>();
    wev_k<<<1, FE * HEADS + FE>>>(We1, ae1, We2, ae2);
    aeproj_k<<<(EE + 7) / 8, 256>>>(ea);
    hist_k<<<(E2 + 255) / 256, 256>>>(ei);
    scan_k<<<1, 1024>>>();
    fill_k<<<(E2 + 255) / 256, 256>>>(ei);

    // layer 1
    sgemm_k<<<dim3(D1 / 128, (NN + 127) / 128), 256>>>(NN, D1, FIN, x, W1, p_h1, nullptr, nullptr, 0);
    sdot_k<HEADS, HID><<<(NN * HEADS + 7) / 8, 256>>>(p_h1, as1, ad1, p_s1, p_d1);
    gat_agg1<<<NN, 256>>>(p_h1, b1, p_out1);

    // layer 2
    sgemm_k<<<dim3(1, (NN + 127) / 128), 256>>>(NN, HID, D1, p_out1, W2, p_h2t, nullptr, nullptr, 0);
    sdot_k<1, HID><<<(NN + 7) / 8, 256>>>(p_h2t, as2, ad2, p_s2, p_d2);
    gat_agg2<<<NN, 128>>>(p_h2t, b2, p_h2);

    // projection head
    sgemm_k<<<dim3(1, (NN + 127) / 128), 256>>>(NN, HID, HID, p_h2, P1, p_z, pb1, pa, 2);
    sgemm_k<<<dim3(1, (NN + 127) / 128), 256>>>(NN, HID, HID, p_z, P2, out, pb2, nullptr, 3);

    // g = sigmoid(mean(h_proj, axis=0))
    colsum_k<<<128, 128>>>(out);
    final_k<<<1, 128>>>(out + (size_t)NN * HID);
}

// round 2
// speedup vs baseline: 1.1473x; 1.1473x over previous
#include <cuda_runtime.h>
#include <cuda_bf16.h>
#include <math.h>
#include <stdint.h>

// ---------------- problem constants ----------------
constexpr int NN   = 20000;    // nodes
constexpr int EE   = 320000;   // edges (before doubling)
constexpr int E2   = 2 * EE;   // doubled edges
constexpr int FIN  = 256;
constexpr int FE   = 32;
constexpr int HID  = 128;
constexpr int HEADS = 4;
constexpr int D1   = HEADS * HID; // 512

// ---------------- device scratch (static, no allocs) ----------------
__device__ __align__(16) float g_h1   [(size_t)NN * D1];   // x@W1
__device__ __align__(16) float g_out1 [(size_t)NN * D1];   // layer1 output (post ELU)
__device__ __align__(16) float g_h2t  [(size_t)NN * HID];  // h@W2
__device__ __align__(16) float g_h2   [(size_t)NN * HID];  // layer2 output (post ELU)
__device__ __align__(16) float g_z    [(size_t)NN * HID];  // proj1 output (post PReLU)
__device__ __align__(16) float g_s1   [NN * HEADS];
__device__ __align__(16) float g_d1   [NN * HEADS];
__device__ float g_s2   [NN];
__device__ float g_d2   [NN];
__device__ float4 g_aep1 [EE];     // per-edge logit contribution, 4 heads
__device__ float  g_aep2 [EE];
__device__ float4 g_w1   [E2];     // per-CSR-slot: logits then normalized weights (4 heads)
__device__ float  g_w2   [E2];     // layer-2 weights per CSR slot
__device__ float g_wev1 [FE * HEADS];
__device__ float g_wev2 [FE];
__device__ int   g_deg  [NN];
__device__ int   g_rowptr[NN + 1];
__device__ int   g_cursor[NN];
__device__ int   g_csrc [E2];
__device__ int   g_ceid [E2];
__device__ float g_colsum[HID];

// ---------------- small helpers ----------------
__global__ void zero_k() {
    int i = blockIdx.x * blockDim.x + threadIdx.x;
    if (i < NN) g_deg[i] = 0;
    if (i < HID) g_colsum[i] = 0.f;
}

// wev1[f*4+h] = sum_c We1[f,h*128+c]*ae1[h,c];  wev2[f] = sum_c We2[f,c]*ae2[c]
__global__ void wev_k(const float* __restrict__ We1, const float* __restrict__ ae1,
                      const float* __restrict__ We2, const float* __restrict__ ae2) {
    int t = threadIdx.x;
    if (t < FE * HEADS) {
        int f = t >> 2, h = t & 3;
        float s = 0.f;
        for (int c = 0; c < HID; c++) s += We1[(size_t)f * D1 + h * HID + c] * ae1[h * HID + c];
        g_wev1[t] = s;
    } else if (t < FE * HEADS + FE) {
        int f = t - FE * HEADS;
        float s = 0.f;
        for (int c = 0; c < HID; c++) s += We2[(size_t)f * HID + c] * ae2[c];
        g_wev2[f] = s;
    }
}

// per-edge logit contributions: aep1[e][h] = ea[e,:] . wev1[:,h]; aep2[e] = ea[e,:] . wev2
__global__ __launch_bounds__(256) void aeproj_k(const float* __restrict__ ea) {
    __shared__ float w1s[FE * HEADS];
    __shared__ float w2s[FE];
    int tid = threadIdx.x;
    if (tid < FE * HEADS) w1s[tid] = g_wev1[tid];
    if (tid < FE)         w2s[tid] = g_wev2[tid];
    __syncthreads();
    int e = blockIdx.x * 8 + (tid >> 5);
    int lane = tid & 31;
    if (e >= EE) return;
    float v = ea[(size_t)e * FE + lane];
    float p0 = v * w1s[lane * 4 + 0];
    float p1 = v * w1s[lane * 4 + 1];
    float p2 = v * w1s[lane * 4 + 2];
    float p3 = v * w1s[lane * 4 + 3];
    float p4 = v * w2s[lane];
    #pragma unroll
    for (int off = 16; off > 0; off >>= 1) {
        p0 += __shfl_down_sync(0xffffffffu, p0, off);
        p1 += __shfl_down_sync(0xffffffffu, p1, off);
        p2 += __shfl_down_sync(0xffffffffu, p2, off);
        p3 += __shfl_down_sync(0xffffffffu, p3, off);
        p4 += __shfl_down_sync(0xffffffffu, p4, off);
    }
    if (lane == 0) {
        g_aep1[e] = make_float4(p0, p1, p2, p3);
        g_aep2[e] = p4;
    }
}

// ---------------- CSR build (by destination) ----------------
__global__ void hist_k(const int* __restrict__ ei) {
    int j = blockIdx.x * blockDim.x + threadIdx.x;
    if (j >= E2) return;
    int dst = (j < EE) ? ei[EE + j] : ei[j - EE];
    atomicAdd(&g_deg[dst], 1);
}

__global__ __launch_bounds__(1024) void scan_k() {
    __shared__ int part[1024];
    int tid = threadIdx.x;
    const int CH = (NN + 1023) / 1024;
    int base = tid * CH;
    int s = 0;
    for (int i = 0; i < CH; i++) {
        int idx = base + i;
        if (idx < NN) s += g_deg[idx];
    }
    part[tid] = s;
    __syncthreads();
    for (int off = 1; off < 1024; off <<= 1) {
        int v = (tid >= off) ? part[tid - off] : 0;
        __syncthreads();
        part[tid] += v;
        __syncthreads();
    }
    int pre = part[tid] - s; // exclusive prefix
    for (int i = 0; i < CH; i++) {
        int idx = base + i;
        if (idx < NN) {
            g_rowptr[idx] = pre;
            g_cursor[idx] = pre;
            pre += g_deg[idx];
        }
    }
    if (tid == 1023) g_rowptr[NN] = part[1023];
}

__global__ void fill_k(const int* __restrict__ ei) {
    int j = blockIdx.x * blockDim.x + threadIdx.x;
    if (j >= E2) return;
    int srcv, dstv, eid;
    if (j < EE) { srcv = ei[j];       dstv = ei[EE + j]; eid = j; }
    else        { int e = j - EE; srcv = ei[EE + e]; dstv = ei[e]; eid = e; }
    int pos = atomicAdd(&g_cursor[dstv], 1);
    g_csrc[pos] = srcv;
    g_ceid[pos] = eid;
}

// ---------------- SGEMM 128x128x8, 256 thr, 8x8 microtile ----------------
// epi: 0 = none, 2 = bias + PReLU(pa[0]), 3 = bias only
// If sOut != nullptr, fused per-row dot products with aS/aD (column tile == head).
__global__ __launch_bounds__(256) void sgemm_k(int M, int N, int K,
        const float* __restrict__ A, const float* __restrict__ B, float* __restrict__ C,
        const float* __restrict__ bias, const float* __restrict__ pa, int epi,
        const float* __restrict__ aS, const float* __restrict__ aD,
        float* __restrict__ sOut, float* __restrict__ dOut, int hs) {
    __shared__ float As[8][128];
    __shared__ float Bs[8][128];
    int tid = threadIdx.x;
    int rowBase = blockIdx.y * 128;
    int colBase = blockIdx.x * 128;
    int aRow = tid >> 1;
    int aCol = (tid & 1) * 4;
    int bRow = tid >> 5;
    int bCol = (tid & 31) * 4;
    int ty = tid >> 4, tx = tid & 15;
    float acc[8][8];
    #pragma unroll
    for (int i = 0; i < 8; i++)
        #pragma unroll
        for (int j = 0; j < 8; j++) acc[i][j] = 0.f;

    for (int k0 = 0; k0 < K; k0 += 8) {
        float4 av = make_float4(0.f, 0.f, 0.f, 0.f);
        int gr = rowBase + aRow;
        if (gr < M) av = *reinterpret_cast<const float4*>(&A[(size_t)gr * K + k0 + aCol]);
        As[aCol + 0][aRow] = av.x;
        As[aCol + 1][aRow] = av.y;
        As[aCol + 2][aRow] = av.z;
        As[aCol + 3][aRow] = av.w;
        float4 bv = *reinterpret_cast<const float4*>(&B[(size_t)(k0 + bRow) * N + colBase + bCol]);
        *reinterpret_cast<float4*>(&Bs[bRow][bCol]) = bv;
        __syncthreads();
        #pragma unroll
        for (int kk = 0; kk < 8; kk++) {
            float ar[8], br[8];
            #pragma unroll
            for (int i = 0; i < 8; i++) ar[i] = As[kk][ty * 8 + i];
            #pragma unroll
            for (int j = 0; j < 8; j++) br[j] = Bs[kk][tx * 8 + j];
            #pragma unroll
            for (int i = 0; i < 8; i++)
                #pragma unroll
                for (int j = 0; j < 8; j++) acc[i][j] += ar[i] * br[j];
        }
        __syncthreads();
    }
    float pav = (epi == 2) ? pa[0] : 0.f;
    #pragma unroll
    for (int i = 0; i < 8; i++) {
        int r = rowBase + ty * 8 + i;
        if (r >= M) continue;
        #pragma unroll
        for (int j = 0; j < 8; j++) {
            int c = colBase + tx * 8 + j;
            float v = acc[i][j];
            if (epi) {
                v += bias[c];
                if (epi == 2) v = v > 0.f ? v : pav * v;
            }
            C[(size_t)r * N + c] = v;
        }
    }
    // fused attention dot products: s[r] = C_row . aS[head], d[r] = C_row . aD[head]
    if (sOut) {
        int head = colBase >> 7;
        float avr[8], dvr[8];
        #pragma unroll
        for (int j = 0; j < 8; j++) {
            avr[j] = aS[colBase + tx * 8 + j];
            dvr[j] = aD[colBase + tx * 8 + j];
        }
        #pragma unroll
        for (int i = 0; i < 8; i++) {
            float ps = 0.f, pd = 0.f;
            #pragma unroll
            for (int j = 0; j < 8; j++) { ps += acc[i][j] * avr[j]; pd += acc[i][j] * dvr[j]; }
            #pragma unroll
            for (int off = 8; off > 0; off >>= 1) {
                ps += __shfl_down_sync(0xffffffffu, ps, off, 16);
                pd += __shfl_down_sync(0xffffffffu, pd, off, 16);
            }
            if (tx == 0) {
                int r = rowBase + ty * 8 + i;
                if (r < M) { sOut[(size_t)r * hs + head] = ps; dOut[(size_t)r * hs + head] = pd; }
            }
        }
    }
}

// ---------------- layer-1 softmax weights: warp per node, 4 heads ----------------
__global__ __launch_bounds__(256) void wcalc1_k() {
    int n = blockIdx.x * 8 + (threadIdx.x >> 5);
    if (n >= NN) return;
    int lane = threadIdx.x & 31;
    int start = g_rowptr[n], end = g_rowptr[n + 1];
    if (start == end) return;
    float dl0 = g_d1[n * 4 + 0], dl1 = g_d1[n * 4 + 1];
    float dl2 = g_d1[n * 4 + 2], dl3 = g_d1[n * 4 + 3];
    float m0 = -INFINITY, m1 = -INFINITY, m2 = -INFINITY, m3 = -INFINITY;
    float s0 = 0.f, s1v = 0.f, s2v = 0.f, s3 = 0.f;
    for (int i = start + lane; i < end; i += 32) {
        int sr = g_csrc[i], e = g_ceid[i];
        float4 ap = g_aep1[e];
        float l0 = g_s1[sr * 4 + 0] + dl0 + ap.x; l0 = l0 > 0.f ? l0 : 0.2f * l0;
        float l1 = g_s1[sr * 4 + 1] + dl1 + ap.y; l1 = l1 > 0.f ? l1 : 0.2f * l1;
        float l2 = g_s1[sr * 4 + 2] + dl2 + ap.z; l2 = l2 > 0.f ? l2 : 0.2f * l2;
        float l3 = g_s1[sr * 4 + 3] + dl3 + ap.w; l3 = l3 > 0.f ? l3 : 0.2f * l3;
        g_w1[i] = make_float4(l0, l1, l2, l3);
        float nm;
        nm = fmaxf(m0, l0); s0  = s0  * __expf(m0 - nm) + __expf(l0 - nm); m0 = nm;
        nm = fmaxf(m1, l1); s1v = s1v * __expf(m1 - nm) + __expf(l1 - nm); m1 = nm;
        nm = fmaxf(m2, l2); s2v = s2v * __expf(m2 - nm) + __expf(l2 - nm); m2 = nm;
        nm = fmaxf(m3, l3); s3  = s3  * __expf(m3 - nm) + __expf(l3 - nm); m3 = nm;
    }
    #pragma unroll
    for (int off = 16; off > 0; off >>= 1) {
        float om, os, nm, a, b;
        om = __shfl_xor_sync(0xffffffffu, m0, off); os = __shfl_xor_sync(0xffffffffu, s0, off);
        nm = fmaxf(m0, om);
        a = (m0 == nm) ? s0 : s0 * __expf(m0 - nm);
        b = (om == nm) ? os : os * __expf(om - nm);
        s0 = a + b; m0 = nm;
        om = __shfl_xor_sync(0xffffffffu, m1, off); os = __shfl_xor_sync(0xffffffffu, s1v, off);
        nm = fmaxf(m1, om);
        a = (m1 == nm) ? s1v : s1v * __expf(m1 - nm);
        b = (om == nm) ? os : os * __expf(om - nm);
        s1v = a + b; m1 = nm;
        om = __shfl_xor_sync(0xffffffffu, m2, off); os = __shfl_xor_sync(0xffffffffu, s2v, off);
        nm = fmaxf(m2, om);
        a = (m2 == nm) ? s2v : s2v * __expf(m2 - nm);
        b = (om == nm) ? os : os * __expf(om - nm);
        s2v = a + b; m2 = nm;
        om = __shfl_xor_sync(0xffffffffu, m3, off); os = __shfl_xor_sync(0xffffffffu, s3, off);
        nm = fmaxf(m3, om);
        a = (m3 == nm) ? s3 : s3 * __expf(m3 - nm);
        b = (om == nm) ? os : os * __expf(om - nm);
        s3 = a + b; m3 = nm;
    }
    float i0 = 1.f / s0, i1 = 1.f / s1v, i2 = 1.f / s2v, i3 = 1.f / s3;
    for (int i = start + lane; i < end; i += 32) {
        float4 l = g_w1[i];
        g_w1[i] = make_float4(__expf(l.x - m0) * i0, __expf(l.y - m1) * i1,
                              __expf(l.z - m2) * i2, __expf(l.w - m3) * i3);
    }
}

// ---------------- layer-2 softmax weights: warp per node, 1 head ----------------
__global__ __launch_bounds__(256) void wcalc2_k() {
    int n = blockIdx.x * 8 + (threadIdx.x >> 5);
    if (n >= NN) return;
    int lane = threadIdx.x & 31;
    int start = g_rowptr[n], end = g_rowptr[n + 1];
    if (start == end) return;
    float dl = g_d2[n];
    float m = -INFINITY, s = 0.f;
    for (int i = start + lane; i < end; i += 32) {
        int sr = g_csrc[i], e = g_ceid[i];
        float l = g_s2[sr] + dl + g_aep2[e];
        l = l > 0.f ? l : 0.2f * l;
        g_w2[i] = l;
        float nm = fmaxf(m, l);
        s = s * __expf(m - nm) + __expf(l - nm);
        m = nm;
    }
    #pragma unroll
    for (int off = 16; off > 0; off >>= 1) {
        float om = __shfl_xor_sync(0xffffffffu, m, off);
        float os = __shfl_xor_sync(0xffffffffu, s, off);
        float nm = fmaxf(m, om);
        float a = (m == nm) ? s : s * __expf(m - nm);
        float b = (om == nm) ? os : os * __expf(om - nm);
        s = a + b; m = nm;
    }
    float inv = 1.f / s;
    for (int i = start + lane; i < end; i += 32)
        g_w2[i] = __expf(g_w2[i] - m) * inv;
}

// ---------------- layer-1 aggregation: pure weighted gather, 512 ch ----------------
__global__ __launch_bounds__(128) void agg1_k(const float* __restrict__ h1,
        const float* __restrict__ bias, float* __restrict__ out) {
    int n = blockIdx.x, tid = threadIdx.x;
    int start = g_rowptr[n], end = g_rowptr[n + 1];
    __shared__ int src_sh[128];
    __shared__ float4 w_sh[128];
    int hsel = tid >> 5;  // head index (warp-uniform)
    float4 acc = make_float4(0.f, 0.f, 0.f, 0.f);
    for (int t0 = start; t0 < end; t0 += 128) {
        int cnt = min(128, end - t0);
        if (tid < cnt) { src_sh[tid] = g_csrc[t0 + tid]; w_sh[tid] = g_w1[t0 + tid]; }
        __syncthreads();
        #pragma unroll 4
        for (int e = 0; e < cnt; e++) {
            int s = src_sh[e];
            float wv = reinterpret_cast<const float*>(&w_sh[e])[hsel];
            float4 hv = *reinterpret_cast<const float4*>(&h1[(size_t)s * D1 + tid * 4]);
            acc.x += hv.x * wv; acc.y += hv.y * wv; acc.z += hv.z * wv; acc.w += hv.w * wv;
        }
        __syncthreads();
    }
    const float4 bv = *reinterpret_cast<const float4*>(&bias[tid * 4]);
    float o0 = acc.x + bv.x, o1 = acc.y + bv.y, o2 = acc.z + bv.z, o3 = acc.w + bv.w;
    o0 = o0 > 0.f ? o0 : (__expf(o0) - 1.f);
    o1 = o1 > 0.f ? o1 : (__expf(o1) - 1.f);
    o2 = o2 > 0.f ? o2 : (__expf(o2) - 1.f);
    o3 = o3 > 0.f ? o3 : (__expf(o3) - 1.f);
    *reinterpret_cast<float4*>(&out[(size_t)n * D1 + tid * 4]) = make_float4(o0, o1, o2, o3);
}

// ---------------- layer-2 aggregation: warp per node, 128 ch ----------------
__global__ __launch_bounds__(256) void agg2_k(const float* __restrict__ h2t,
        const float* __restrict__ bias, float* __restrict__ out) {
    int n = blockIdx.x * 8 + (threadIdx.x >> 5);
    if (n >= NN) return;
    int lane = threadIdx.x & 31;
    int start = g_rowptr[n], end = g_rowptr[n + 1];
    float4 acc = make_float4(0.f, 0.f, 0.f, 0.f);
    for (int t0 = start; t0 < end; t0 += 32) {
        int cnt = min(32, end - t0);
        int sr = 0; float wv = 0.f;
        if (lane < cnt) { sr = g_csrc[t0 + lane]; wv = g_w2[t0 + lane]; }
        for (int j = 0; j < cnt; j++) {
            int s = __shfl_sync(0xffffffffu, sr, j);
            float w = __shfl_sync(0xffffffffu, wv, j);
            float4 hv = *reinterpret_cast<const float4*>(&h2t[(size_t)s * HID + lane * 4]);
            acc.x += hv.x * w; acc.y += hv.y * w; acc.z += hv.z * w; acc.w += hv.w * w;
        }
    }
    const float4 bv = *reinterpret_cast<const float4*>(&bias[lane * 4]);
    float o0 = acc.x + bv.x, o1 = acc.y + bv.y, o2 = acc.z + bv.z, o3 = acc.w + bv.w;
    o0 = o0 > 0.f ? o0 : (__expf(o0) - 1.f);
    o1 = o1 > 0.f ? o1 : (__expf(o1) - 1.f);
    o2 = o2 > 0.f ? o2 : (__expf(o2) - 1.f);
    o3 = o3 > 0.f ? o3 : (__expf(o3) - 1.f);
    *reinterpret_cast<float4*>(&out[(size_t)n * HID + lane * 4]) = make_float4(o0, o1, o2, o3);
}

// ---------------- column mean + sigmoid ----------------
__global__ void colsum_k(const float* __restrict__ hp) {
    int col = threadIdx.x;
    float acc = 0.f;
    for (int r = blockIdx.x; r < NN; r += gridDim.x) acc += hp[(size_t)r * HID + col];
    atomicAdd(&g_colsum[col], acc);
}

__global__ void final_k(float* __restrict__ outg) {
    int t = threadIdx.x;
    if (t < HID) {
        float m = g_colsum[t] / (float)NN;
        outg[t] = 1.f / (1.f + __expf(-m));
    }
}

// ---------------- launch ----------------
extern "C" void kernel_launch(void* const* d_in, const int* in_sizes, int n_in,
                              void* d_out, int out_size) {
    const float* x   = (const float*)d_in[0];
    const int*   ei  = (const int*)  d_in[1];
    const float* ea  = (const float*)d_in[2];
    const float* W1  = (const float*)d_in[3];
    const float* We1 = (const float*)d_in[4];
    const float* as1 = (const float*)d_in[5];
    const float* ad1 = (const float*)d_in[6];
    const float* ae1 = (const float*)d_in[7];
    const float* b1  = (const float*)d_in[8];
    const float* W2  = (const float*)d_in[9];
    const float* We2 = (const float*)d_in[10];
    const float* as2 = (const float*)d_in[11];
    const float* ad2 = (const float*)d_in[12];
    const float* ae2 = (const float*)d_in[13];
    const float* b2  = (const float*)d_in[14];
    const float* P1  = (const float*)d_in[15];
    const float* pb1 = (const float*)d_in[16];
    const float* pa  = (const float*)d_in[17];
    const float* P2  = (const float*)d_in[18];
    const float* pb2 = (const float*)d_in[19];
    float* out = (float*)d_out;

    float *p_h1, *p_out1, *p_h2t, *p_h2, *p_z, *p_s1, *p_d1, *p_s2, *p_d2;
    cudaGetSymbolAddress((void**)&p_h1,   g_h1);
    cudaGetSymbolAddress((void**)&p_out1, g_out1);
    cudaGetSymbolAddress((void**)&p_h2t,  g_h2t);
    cudaGetSymbolAddress((void**)&p_h2,   g_h2);
    cudaGetSymbolAddress((void**)&p_z,    g_z);
    cudaGetSymbolAddress((void**)&p_s1,   g_s1);
    cudaGetSymbolAddress((void**)&p_d1,   g_d1);
    cudaGetSymbolAddress((void**)&p_s2,   g_s2);
    cudaGetSymbolAddress((void**)&p_d2,   g_d2);

    zero_k<<<(NN + 255) / 256, 256>>>();
    wev_k<<<1, FE * HEADS + FE>>>(We1, ae1, We2, ae2);
    aeproj_k<<<(EE + 7) / 8, 256>>>(ea);
    hist_k<<<(E2 + 255) / 256, 256>>>(ei);
    scan_k<<<1, 1024>>>();
    fill_k<<<(E2 + 255) / 256, 256>>>(ei);

    // layer 1: GEMM with fused attention dots
    sgemm_k<<<dim3(D1 / 128, (NN + 127) / 128), 256>>>(NN, D1, FIN, x, W1, p_h1,
            nullptr, nullptr, 0, as1, ad1, p_s1, p_d1, HEADS);
    wcalc1_k<<<(NN + 7) / 8, 256>>>();
    agg1_k<<<NN, 128>>>(p_h1, b1, p_out1);

    // layer 2
    sgemm_k<<<dim3(1, (NN + 127) / 128), 256>>>(NN, HID, D1, p_out1, W2, p_h2t,
            nullptr, nullptr, 0, as2, ad2, p_s2, p_d2, 1);
    wcalc2_k<<<(NN + 7) / 8, 256>>>();
    agg2_k<<<(NN + 7) / 8, 256>>>(p_h2t, b2, p_h2);

    // projection head
    sgemm_k<<<dim3(1, (NN + 127) / 128), 256>>>(NN, HID, HID, p_h2, P1, p_z,
            pb1, pa, 2, nullptr, nullptr, nullptr, nullptr, 1);
    sgemm_k<<<dim3(1, (NN + 127) / 128), 256>>>(NN, HID, HID, p_z, P2, out,
            pb2, nullptr, 3, nullptr, nullptr, nullptr, nullptr, 1);

    // g = sigmoid(mean(h_proj, axis=0))
    colsum_k<<<128, 128>>>(out);
    final_k<<<1, 128>>>(out + (size_t)NN * HID);
}

// round 3
// speedup vs baseline: 1.1474x; 1.0000x over previous
#include <cuda_runtime.h>
#include <cuda_bf16.h>
#include <math.h>
#include <stdint.h>

// ---------------- problem constants ----------------
constexpr int NN   = 20000;    // nodes
constexpr int EE   = 320000;   // edges (before doubling)
constexpr int E2   = 2 * EE;   // doubled edges
constexpr int FIN  = 256;
constexpr int FE   = 32;
constexpr int HID  = 128;
constexpr int HEADS = 4;
constexpr int D1   = HEADS * HID; // 512

// ---------------- device scratch (static, no allocs) ----------------
__device__ __align__(16) float g_h1   [(size_t)NN * D1];   // x@W1
__device__ __align__(16) float g_out1 [(size_t)NN * D1];   // layer1 output (post ELU)
__device__ __align__(16) float g_h2t  [(size_t)NN * HID];  // h@W2
__device__ __align__(16) float g_h2   [(size_t)NN * HID];  // layer2 output (post ELU)
__device__ __align__(16) float g_z    [(size_t)NN * HID];  // proj1 output (post PReLU)
__device__ __align__(16) float g_s1   [NN * HEADS];
__device__ __align__(16) float g_d1   [NN * HEADS];
__device__ float g_s2   [NN];
__device__ float g_d2   [NN];
__device__ float4 g_aep1 [EE];     // per-edge logit contribution, 4 heads
__device__ float  g_aep2 [EE];
__device__ float4 g_w1   [E2];     // per-CSR-slot: logits then normalized weights (4 heads)
__device__ float  g_w2   [E2];     // layer-2 weights per CSR slot
__device__ float g_wev1 [FE * HEADS];
__device__ float g_wev2 [FE];
__device__ int   g_deg  [NN];
__device__ int   g_rowptr[NN + 1];
__device__ int   g_cursor[NN];
__device__ int   g_csrc [E2];
__device__ int   g_ceid [E2];
__device__ float g_colsum[HID];

// ---------------- small helpers ----------------
__global__ void zero_k() {
    int i = blockIdx.x * blockDim.x + threadIdx.x;
    if (i < NN) g_deg[i] = 0;
    if (i < HID) g_colsum[i] = 0.f;
}

// wev1[f*4+h] = sum_c We1[f,h*128+c]*ae1[h,c];  wev2[f] = sum_c We2[f,c]*ae2[c]
__global__ void wev_k(const float* __restrict__ We1, const float* __restrict__ ae1,
                      const float* __restrict__ We2, const float* __restrict__ ae2) {
    int t = threadIdx.x;
    if (t < FE * HEADS) {
        int f = t >> 2, h = t & 3;
        float s = 0.f;
        for (int c = 0; c < HID; c++) s += We1[(size_t)f * D1 + h * HID + c] * ae1[h * HID + c];
        g_wev1[t] = s;
    } else if (t < FE * HEADS + FE) {
        int f = t - FE * HEADS;
        float s = 0.f;
        for (int c = 0; c < HID; c++) s += We2[(size_t)f * HID + c] * ae2[c];
        g_wev2[f] = s;
    }
}

// per-edge logit contributions: aep1[e][h] = ea[e,:] . wev1[:,h]; aep2[e] = ea[e,:] . wev2
__global__ __launch_bounds__(256) void aeproj_k(const float* __restrict__ ea) {
    __shared__ float w1s[FE * HEADS];
    __shared__ float w2s[FE];
    int tid = threadIdx.x;
    if (tid < FE * HEADS) w1s[tid] = g_wev1[tid];
    if (tid < FE)         w2s[tid] = g_wev2[tid];
    __syncthreads();
    int e = blockIdx.x * 8 + (tid >> 5);
    int lane = tid & 31;
    if (e >= EE) return;
    float v = ea[(size_t)e * FE + lane];
    float p0 = v * w1s[lane * 4 + 0];
    float p1 = v * w1s[lane * 4 + 1];
    float p2 = v * w1s[lane * 4 + 2];
    float p3 = v * w1s[lane * 4 + 3];
    float p4 = v * w2s[lane];
    #pragma unroll
    for (int off = 16; off > 0; off >>= 1) {
        p0 += __shfl_down_sync(0xffffffffu, p0, off);
        p1 += __shfl_down_sync(0xffffffffu, p1, off);
        p2 += __shfl_down_sync(0xffffffffu, p2, off);
        p3 += __shfl_down_sync(0xffffffffu, p3, off);
        p4 += __shfl_down_sync(0xffffffffu, p4, off);
    }
    if (lane == 0) {
        g_aep1[e] = make_float4(p0, p1, p2, p3);
        g_aep2[e] = p4;
    }
}

// ---------------- CSR build (by destination) ----------------
__global__ void hist_k(const int* __restrict__ ei) {
    int j = blockIdx.x * blockDim.x + threadIdx.x;
    if (j >= E2) return;
    int dst = (j < EE) ? ei[EE + j] : ei[j - EE];
    atomicAdd(&g_deg[dst], 1);
}

__global__ __launch_bounds__(1024) void scan_k() {
    __shared__ int part[1024];
    int tid = threadIdx.x;
    const int CH = (NN + 1023) / 1024;
    int base = tid * CH;
    int s = 0;
    for (int i = 0; i < CH; i++) {
        int idx = base + i;
        if (idx < NN) s += g_deg[idx];
    }
    part[tid] = s;
    __syncthreads();
    for (int off = 1; off < 1024; off <<= 1) {
        int v = (tid >= off) ? part[tid - off] : 0;
        __syncthreads();
        part[tid] += v;
        __syncthreads();
    }
    int pre = part[tid] - s; // exclusive prefix
    for (int i = 0; i < CH; i++) {
        int idx = base + i;
        if (idx < NN) {
            g_rowptr[idx] = pre;
            g_cursor[idx] = pre;
            pre += g_deg[idx];
        }
    }
    if (tid == 1023) g_rowptr[NN] = part[1023];
}

__global__ void fill_k(const int* __restrict__ ei) {
    int j = blockIdx.x * blockDim.x + threadIdx.x;
    if (j >= E2) return;
    int srcv, dstv, eid;
    if (j < EE) { srcv = ei[j];       dstv = ei[EE + j]; eid = j; }
    else        { int e = j - EE; srcv = ei[EE + e]; dstv = ei[e]; eid = e; }
    int pos = atomicAdd(&g_cursor[dstv], 1);
    g_csrc[pos] = srcv;
    g_ceid[pos] = eid;
}

// ---------------- SGEMM 128x128x8, 256 thr, 8x8 microtile ----------------
// epi: 0 = none, 2 = bias + PReLU(pa[0]), 3 = bias only
// If sOut != nullptr, fused per-row dot products with aS/aD (column tile == head).
__global__ __launch_bounds__(256) void sgemm_k(int M, int N, int K,
        const float* __restrict__ A, const float* __restrict__ B, float* __restrict__ C,
        const float* __restrict__ bias, const float* __restrict__ pa, int epi,
        const float* __restrict__ aS, const float* __restrict__ aD,
        float* __restrict__ sOut, float* __restrict__ dOut, int hs) {
    __shared__ float As[8][128];
    __shared__ float Bs[8][128];
    int tid = threadIdx.x;
    int rowBase = blockIdx.y * 128;
    int colBase = blockIdx.x * 128;
    int aRow = tid >> 1;
    int aCol = (tid & 1) * 4;
    int bRow = tid >> 5;
    int bCol = (tid & 31) * 4;
    int ty = tid >> 4, tx = tid & 15;
    float acc[8][8];
    #pragma unroll
    for (int i = 0; i < 8; i++)
        #pragma unroll
        for (int j = 0; j < 8; j++) acc[i][j] = 0.f;

    for (int k0 = 0; k0 < K; k0 += 8) {
        float4 av = make_float4(0.f, 0.f, 0.f, 0.f);
        int gr = rowBase + aRow;
        if (gr < M) av = *reinterpret_cast<const float4*>(&A[(size_t)gr * K + k0 + aCol]);
        As[aCol + 0][aRow] = av.x;
        As[aCol + 1][aRow] = av.y;
        As[aCol + 2][aRow] = av.z;
        As[aCol + 3][aRow] = av.w;
        float4 bv = *reinterpret_cast<const float4*>(&B[(size_t)(k0 + bRow) * N + colBase + bCol]);
        *reinterpret_cast<float4*>(&Bs[bRow][bCol]) = bv;
        __syncthreads();
        #pragma unroll
        for (int kk = 0; kk < 8; kk++) {
            float ar[8], br[8];
            #pragma unroll
            for (int i = 0; i < 8; i++) ar[i] = As[kk][ty * 8 + i];
            #pragma unroll
            for (int j = 0; j < 8; j++) br[j] = Bs[kk][tx * 8 + j];
            #pragma unroll
            for (int i = 0; i < 8; i++)
                #pragma unroll
                for (int j = 0; j < 8; j++) acc[i][j] += ar[i] * br[j];
        }
        __syncthreads();
    }
    float pav = (epi == 2) ? pa[0] : 0.f;
    #pragma unroll
    for (int i = 0; i < 8; i++) {
        int r = rowBase + ty * 8 + i;
        if (r >= M) continue;
        #pragma unroll
        for (int j = 0; j < 8; j++) {
            int c = colBase + tx * 8 + j;
            float v = acc[i][j];
            if (epi) {
                v += bias[c];
                if (epi == 2) v = v > 0.f ? v : pav * v;
            }
            C[(size_t)r * N + c] = v;
        }
    }
    // fused attention dot products: s[r] = C_row . aS[head], d[r] = C_row . aD[head]
    if (sOut) {
        int head = colBase >> 7;
        float avr[8], dvr[8];
        #pragma unroll
        for (int j = 0; j < 8; j++) {
            avr[j] = aS[colBase + tx * 8 + j];
            dvr[j] = aD[colBase + tx * 8 + j];
        }
        #pragma unroll
        for (int i = 0; i < 8; i++) {
            float ps = 0.f, pd = 0.f;
            #pragma unroll
            for (int j = 0; j < 8; j++) { ps += acc[i][j] * avr[j]; pd += acc[i][j] * dvr[j]; }
            #pragma unroll
            for (int off = 8; off > 0; off >>= 1) {
                ps += __shfl_down_sync(0xffffffffu, ps, off, 16);
                pd += __shfl_down_sync(0xffffffffu, pd, off, 16);
            }
            if (tx == 0) {
                int r = rowBase + ty * 8 + i;
                if (r < M) { sOut[(size_t)r * hs + head] = ps; dOut[(size_t)r * hs + head] = pd; }
            }
        }
    }
}

// ---------------- layer-1 softmax weights: warp per node, 4 heads ----------------
__global__ __launch_bounds__(256) void wcalc1_k() {
    int n = blockIdx.x * 8 + (threadIdx.x >> 5);
    if (n >= NN) return;
    int lane = threadIdx.x & 31;
    int start = g_rowptr[n], end = g_rowptr[n + 1];
    if (start == end) return;
    float dl0 = g_d1[n * 4 + 0], dl1 = g_d1[n * 4 + 1];
    float dl2 = g_d1[n * 4 + 2], dl3 = g_d1[n * 4 + 3];
    float m0 = -INFINITY, m1 = -INFINITY, m2 = -INFINITY, m3 = -INFINITY;
    float s0 = 0.f, s1v = 0.f, s2v = 0.f, s3 = 0.f;
    for (int i = start + lane; i < end; i += 32) {
        int sr = g_csrc[i], e = g_ceid[i];
        float4 ap = g_aep1[e];
        float l0 = g_s1[sr * 4 + 0] + dl0 + ap.x; l0 = l0 > 0.f ? l0 : 0.2f * l0;
        float l1 = g_s1[sr * 4 + 1] + dl1 + ap.y; l1 = l1 > 0.f ? l1 : 0.2f * l1;
        float l2 = g_s1[sr * 4 + 2] + dl2 + ap.z; l2 = l2 > 0.f ? l2 : 0.2f * l2;
        float l3 = g_s1[sr * 4 + 3] + dl3 + ap.w; l3 = l3 > 0.f ? l3 : 0.2f * l3;
        g_w1[i] = make_float4(l0, l1, l2, l3);
        float nm;
        nm = fmaxf(m0, l0); s0  = s0  * __expf(m0 - nm) + __expf(l0 - nm); m0 = nm;
        nm = fmaxf(m1, l1); s1v = s1v * __expf(m1 - nm) + __expf(l1 - nm); m1 = nm;
        nm = fmaxf(m2, l2); s2v = s2v * __expf(m2 - nm) + __expf(l2 - nm); m2 = nm;
        nm = fmaxf(m3, l3); s3  = s3  * __expf(m3 - nm) + __expf(l3 - nm); m3 = nm;
    }
    #pragma unroll
    for (int off = 16; off > 0; off >>= 1) {
        float om, os, nm, a, b;
        om = __shfl_xor_sync(0xffffffffu, m0, off); os = __shfl_xor_sync(0xffffffffu, s0, off);
        nm = fmaxf(m0, om);
        a = (m0 == nm) ? s0 : s0 * __expf(m0 - nm);
        b = (om == nm) ? os : os * __expf(om - nm);
        s0 = a + b; m0 = nm;
        om = __shfl_xor_sync(0xffffffffu, m1, off); os = __shfl_xor_sync(0xffffffffu, s1v, off);
        nm = fmaxf(m1, om);
        a = (m1 == nm) ? s1v : s1v * __expf(m1 - nm);
        b = (om == nm) ? os : os * __expf(om - nm);
        s1v = a + b; m1 = nm;
        om = __shfl_xor_sync(0xffffffffu, m2, off); os = __shfl_xor_sync(0xffffffffu, s2v, off);
        nm = fmaxf(m2, om);
        a = (m2 == nm) ? s2v : s2v * __expf(m2 - nm);
        b = (om == nm) ? os : os * __expf(om - nm);
        s2v = a + b; m2 = nm;
        om = __shfl_xor_sync(0xffffffffu, m3, off); os = __shfl_xor_sync(0xffffffffu, s3, off);
        nm = fmaxf(m3, om);
        a = (m3 == nm) ? s3 : s3 * __expf(m3 - nm);
        b = (om == nm) ? os : os * __expf(om - nm);
        s3 = a + b; m3 = nm;
    }
    float i0 = 1.f / s0, i1 = 1.f / s1v, i2 = 1.f / s2v, i3 = 1.f / s3;
    for (int i = start + lane; i < end; i += 32) {
        float4 l = g_w1[i];
        g_w1[i] = make_float4(__expf(l.x - m0) * i0, __expf(l.y - m1) * i1,
                              __expf(l.z - m2) * i2, __expf(l.w - m3) * i3);
    }
}

// ---------------- layer-2 softmax weights: warp per node, 1 head ----------------
__global__ __launch_bounds__(256) void wcalc2_k() {
    int n = blockIdx.x * 8 + (threadIdx.x >> 5);
    if (n >= NN) return;
    int lane = threadIdx.x & 31;
    int start = g_rowptr[n], end = g_rowptr[n + 1];
    if (start == end) return;
    float dl = g_d2[n];
    float m = -INFINITY, s = 0.f;
    for (int i = start + lane; i < end; i += 32) {
        int sr = g_csrc[i], e = g_ceid[i];
        float l = g_s2[sr] + dl + g_aep2[e];
        l = l > 0.f ? l : 0.2f * l;
        g_w2[i] = l;
        float nm = fmaxf(m, l);
        s = s * __expf(m - nm) + __expf(l - nm);
        m = nm;
    }
    #pragma unroll
    for (int off = 16; off > 0; off >>= 1) {
        float om = __shfl_xor_sync(0xffffffffu, m, off);
        float os = __shfl_xor_sync(0xffffffffu, s, off);
        float nm = fmaxf(m, om);
        float a = (m == nm) ? s : s * __expf(m - nm);
        float b = (om == nm) ? os : os * __expf(om - nm);
        s = a + b; m = nm;
    }
    float inv = 1.f / s;
    for (int i = start + lane; i < end; i += 32)
        g_w2[i] = __expf(g_w2[i] - m) * inv;
}

// ---------------- layer-1 aggregation: pure weighted gather, 512 ch ----------------
__global__ __launch_bounds__(128) void agg1_k(const float* __restrict__ h1,
        const float* __restrict__ bias, float* __restrict__ out) {
    int n = blockIdx.x, tid = threadIdx.x;
    int start = g_rowptr[n], end = g_rowptr[n + 1];
    __shared__ int src_sh[128];
    __shared__ float4 w_sh[128];
    int hsel = tid >> 5;  // head index (warp-uniform)
    float4 acc = make_float4(0.f, 0.f, 0.f, 0.f);
    for (int t0 = start; t0 < end; t0 += 128) {
        int cnt = min(128, end - t0);
        if (tid < cnt) { src_sh[tid] = g_csrc[t0 + tid]; w_sh[tid] = g_w1[t0 + tid]; }
        __syncthreads();
        #pragma unroll 4
        for (int e = 0; e < cnt; e++) {
            int s = src_sh[e];
            float wv = reinterpret_cast<const float*>(&w_sh[e])[hsel];
            float4 hv = *reinterpret_cast<const float4*>(&h1[(size_t)s * D1 + tid * 4]);
            acc.x += hv.x * wv; acc.y += hv.y * wv; acc.z += hv.z * wv; acc.w += hv.w * wv;
        }
        __syncthreads();
    }
    const float4 bv = *reinterpret_cast<const float4*>(&bias[tid * 4]);
    float o0 = acc.x + bv.x, o1 = acc.y + bv.y, o2 = acc.z + bv.z, o3 = acc.w + bv.w;
    o0 = o0 > 0.f ? o0 : (__expf(o0) - 1.f);
    o1 = o1 > 0.f ? o1 : (__expf(o1) - 1.f);
    o2 = o2 > 0.f ? o2 : (__expf(o2) - 1.f);
    o3 = o3 > 0.f ? o3 : (__expf(o3) - 1.f);
    *reinterpret_cast<float4*>(&out[(size_t)n * D1 + tid * 4]) = make_float4(o0, o1, o2, o3);
}

// ---------------- layer-2 aggregation: warp per node, 128 ch ----------------
__global__ __launch_bounds__(256) void agg2_k(const float* __restrict__ h2t,
        const float* __restrict__ bias, float* __restrict__ out) {
    int n = blockIdx.x * 8 + (threadIdx.x >> 5);
    if (n >= NN) return;
    int lane = threadIdx.x & 31;
    int start = g_rowptr[n], end = g_rowptr[n + 1];
    float4 acc = make_float4(0.f, 0.f, 0.f, 0.f);
    for (int t0 = start; t0 < end; t0 += 32) {
        int cnt = min(32, end - t0);
        int sr = 0; float wv = 0.f;
        if (lane < cnt) { sr = g_csrc[t0 + lane]; wv = g_w2[t0 + lane]; }
        for (int j = 0; j < cnt; j++) {
            int s = __shfl_sync(0xffffffffu, sr, j);
            float w = __shfl_sync(0xffffffffu, wv, j);
            float4 hv = *reinterpret_cast<const float4*>(&h2t[(size_t)s * HID + lane * 4]);
            acc.x += hv.x * w; acc.y += hv.y * w; acc.z += hv.z * w; acc.w += hv.w * w;
        }
    }
    const float4 bv = *reinterpret_cast<const float4*>(&bias[lane * 4]);
    float o0 = acc.x + bv.x, o1 = acc.y + bv.y, o2 = acc.z + bv.z, o3 = acc.w + bv.w;
    o0 = o0 > 0.f ? o0 : (__expf(o0) - 1.f);
    o1 = o1 > 0.f ? o1 : (__expf(o1) - 1.f);
    o2 = o2 > 0.f ? o2 : (__expf(o2) - 1.f);
    o3 = o3 > 0.f ? o3 : (__expf(o3) - 1.f);
    *reinterpret_cast<float4*>(&out[(size_t)n * HID + lane * 4]) = make_float4(o0, o1, o2, o3);
}

// ---------------- column mean + sigmoid ----------------
__global__ void colsum_k(const float* __restrict__ hp) {
    int col = threadIdx.x;
    float acc = 0.f;
    for (int r = blockIdx.x; r < NN; r += gridDim.x) acc += hp[(size_t)r * HID + col];
    atomicAdd(&g_colsum[col], acc);
}

__global__ void final_k(float* __restrict__ outg) {
    int t = threadIdx.x;
    if (t < HID) {
        float m = g_colsum[t] / (float)NN;
        outg[t] = 1.f / (1.f + __expf(-m));
    }
}

// ---------------- launch ----------------
extern "C" void kernel_launch(void* const* d_in, const int* in_sizes, int n_in,
                              void* d_out, int out_size) {
    const float* x   = (const float*)d_in[0];
    const int*   ei  = (const int*)  d_in[1];
    const float* ea  = (const float*)d_in[2];
    const float* W1  = (const float*)d_in[3];
    const float* We1 = (const float*)d_in[4];
    const float* as1 = (const float*)d_in[5];
    const float* ad1 = (const float*)d_in[6];
    const float* ae1 = (const float*)d_in[7];
    const float* b1  = (const float*)d_in[8];
    const float* W2  = (const float*)d_in[9];
    const float* We2 = (const float*)d_in[10];
    const float* as2 = (const float*)d_in[11];
    const float* ad2 = (const float*)d_in[12];
    const float* ae2 = (const float*)d_in[13];
    const float* b2  = (const float*)d_in[14];
    const float* P1  = (const float*)d_in[15];
    const float* pb1 = (const float*)d_in[16];
    const float* pa  = (const float*)d_in[17];
    const float* P2  = (const float*)d_in[18];
    const float* pb2 = (const float*)d_in[19];
    float* out = (float*)d_out;

    float *p_h1, *p_out1, *p_h2t, *p_h2, *p_z, *p_s1, *p_d1, *p_s2, *p_d2;
    cudaGetSymbolAddress((void**)&p_h1,   g_h1);
    cudaGetSymbolAddress((void**)&p_out1, g_out1);
    cudaGetSymbolAddress((void**)&p_h2t,  g_h2t);
    cudaGetSymbolAddress((void**)&p_h2,   g_h2);
    cudaGetSymbolAddress((void**)&p_z,    g_z);
    cudaGetSymbolAddress((void**)&p_s1,   g_s1);
    cudaGetSymbolAddress((void**)&p_d1,   g_d1);
    cudaGetSymbolAddress((void**)&p_s2,   g_s2);
    cudaGetSymbolAddress((void**)&p_d2,   g_d2);

    zero_k<<<(NN + 255) / 256, 256>>>();
    wev_k<<<1, FE * HEADS + FE>>>(We1, ae1, We2, ae2);
    aeproj_k<<<(EE + 7) / 8, 256>>>(ea);
    hist_k<<<(E2 + 255) / 256, 256>>>(ei);
    scan_k<<<1, 1024>>>();
    fill_k<<<(E2 + 255) / 256, 256>>>(ei);

    // layer 1: GEMM with fused attention dots
    sgemm_k<<<dim3(D1 / 128, (NN + 127) / 128), 256>>>(NN, D1, FIN, x, W1, p_h1,
            nullptr, nullptr, 0, as1, ad1, p_s1, p_d1, HEADS);
    wcalc1_k<<<(NN + 7) / 8, 256>>>();
    agg1_k<<<NN, 128>>>(p_h1, b1, p_out1);

    // layer 2
    sgemm_k<<<dim3(1, (NN + 127) / 128), 256>>>(NN, HID, D1, p_out1, W2, p_h2t,
            nullptr, nullptr, 0, as2, ad2, p_s2, p_d2, 1);
    wcalc2_k<<<(NN + 7) / 8, 256>>>();
    agg2_k<<<(NN + 7) / 8, 256>>>(p_h2t, b2, p_h2);

    // projection head
    sgemm_k<<<dim3(1, (NN + 127) / 128), 256>>>(NN, HID, HID, p_h2, P1, p_z,
            pb1, pa, 2, nullptr, nullptr, nullptr, nullptr, 1);
    sgemm_k<<<dim3(1, (NN + 127) / 128), 256>>>(NN, HID, HID, p_z, P2, out,
            pb2, nullptr, 3, nullptr, nullptr, nullptr, nullptr, 1);

    // g = sigmoid(mean(h_proj, axis=0))
    colsum_k<<<128, 128>>>(out);
    final_k<<<1, 128>>>(out + (size_t)NN * HID);
}

// round 4
// speedup vs baseline: 1.2068x; 1.0518x over previous
#include <cuda_runtime.h>
#include <cuda_bf16.h>
#include <math.h>
#include <stdint.h>

// ---------------- problem constants ----------------
constexpr int NN   = 20000;    // nodes
constexpr int EE   = 320000;   // edges (before doubling)
constexpr int E2   = 2 * EE;   // doubled edges
constexpr int FIN  = 256;
constexpr int FE   = 32;
constexpr int HID  = 128;
constexpr int HEADS = 4;
constexpr int D1   = HEADS * HID; // 512

typedef unsigned long long ull;

// ---------------- device scratch (static, no allocs) ----------------
__device__ __align__(16) float g_h1   [(size_t)NN * D1];   // x@W1
__device__ __align__(16) float g_out1 [(size_t)NN * D1];   // layer1 output (post ELU)
__device__ __align__(16) float g_h2t  [(size_t)NN * HID];  // h@W2
__device__ __align__(16) float g_h2   [(size_t)NN * HID];  // layer2 output (post ELU)
__device__ __align__(16) float g_z    [(size_t)NN * HID];  // proj1 output (post PReLU)
__device__ __align__(16) float g_s1   [NN * HEADS];
__device__ __align__(16) float g_d1   [NN * HEADS];
__device__ float g_s2   [NN];
__device__ float g_d2   [NN];
__device__ float4 g_aep1 [EE];     // per-edge logit contribution, 4 heads
__device__ float  g_aep2 [EE];
__device__ float4 g_w1   [E2];     // per-CSR-slot: logits then normalized weights (4 heads)
__device__ float  g_w2   [E2];     // layer-2 weights per CSR slot
__device__ float g_wev1 [FE * HEADS];
__device__ float g_wev2 [FE];
__device__ int   g_deg  [NN];
__device__ int   g_rowptr[NN + 1];
__device__ int   g_cursor[NN];
__device__ int   g_csrc [E2];
__device__ int   g_ceid [E2];
__device__ float g_colsum[HID];

// ---------------- small helpers ----------------
__global__ void zero_k() {
    int i = blockIdx.x * blockDim.x + threadIdx.x;
    if (i < NN) g_deg[i] = 0;
    if (i < HID) g_colsum[i] = 0.f;
}

// wev1[f*4+h] = sum_c We1[f,h*128+c]*ae1[h,c];  wev2[f] = sum_c We2[f,c]*ae2[c]
__global__ void wev_k(const float* __restrict__ We1, const float* __restrict__ ae1,
                      const float* __restrict__ We2, const float* __restrict__ ae2) {
    int t = threadIdx.x;
    if (t < FE * HEADS) {
        int f = t >> 2, h = t & 3;
        float s = 0.f;
        for (int c = 0; c < HID; c++) s += We1[(size_t)f * D1 + h * HID + c] * ae1[h * HID + c];
        g_wev1[t] = s;
    } else if (t < FE * HEADS + FE) {
        int f = t - FE * HEADS;
        float s = 0.f;
        for (int c = 0; c < HID; c++) s += We2[(size_t)f * HID + c] * ae2[c];
        g_wev2[f] = s;
    }
}

// per-edge logit contributions: aep1[e][h] = ea[e,:] . wev1[:,h]; aep2[e] = ea[e,:] . wev2
__global__ __launch_bounds__(256) void aeproj_k(const float* __restrict__ ea) {
    __shared__ float w1s[FE * HEADS];
    __shared__ float w2s[FE];
    int tid = threadIdx.x;
    if (tid < FE * HEADS) w1s[tid] = g_wev1[tid];
    if (tid < FE)         w2s[tid] = g_wev2[tid];
    __syncthreads();
    int e = blockIdx.x * 8 + (tid >> 5);
    int lane = tid & 31;
    if (e >= EE) return;
    float v = ea[(size_t)e * FE + lane];
    float p0 = v * w1s[lane * 4 + 0];
    float p1 = v * w1s[lane * 4 + 1];
    float p2 = v * w1s[lane * 4 + 2];
    float p3 = v * w1s[lane * 4 + 3];
    float p4 = v * w2s[lane];
    #pragma unroll
    for (int off = 16; off > 0; off >>= 1) {
        p0 += __shfl_down_sync(0xffffffffu, p0, off);
        p1 += __shfl_down_sync(0xffffffffu, p1, off);
        p2 += __shfl_down_sync(0xffffffffu, p2, off);
        p3 += __shfl_down_sync(0xffffffffu, p3, off);
        p4 += __shfl_down_sync(0xffffffffu, p4, off);
    }
    if (lane == 0) {
        g_aep1[e] = make_float4(p0, p1, p2, p3);
        g_aep2[e] = p4;
    }
}

// ---------------- CSR build (by destination) ----------------
__global__ void hist_k(const int* __restrict__ ei) {
    int j = blockIdx.x * blockDim.x + threadIdx.x;
    if (j >= E2) return;
    int dst = (j < EE) ? ei[EE + j] : ei[j - EE];
    atomicAdd(&g_deg[dst], 1);
}

__global__ __launch_bounds__(1024) void scan_k() {
    __shared__ int part[1024];
    int tid = threadIdx.x;
    const int CH = (NN + 1023) / 1024;
    int base = tid * CH;
    int s = 0;
    for (int i = 0; i < CH; i++) {
        int idx = base + i;
        if (idx < NN) s += g_deg[idx];
    }
    part[tid] = s;
    __syncthreads();
    for (int off = 1; off < 1024; off <<= 1) {
        int v = (tid >= off) ? part[tid - off] : 0;
        __syncthreads();
        part[tid] += v;
        __syncthreads();
    }
    int pre = part[tid] - s; // exclusive prefix
    for (int i = 0; i < CH; i++) {
        int idx = base + i;
        if (idx < NN) {
            g_rowptr[idx] = pre;
            g_cursor[idx] = pre;
            pre += g_deg[idx];
        }
    }
    if (tid == 1023) g_rowptr[NN] = part[1023];
}

__global__ void fill_k(const int* __restrict__ ei) {
    int j = blockIdx.x * blockDim.x + threadIdx.x;
    if (j >= E2) return;
    int srcv, dstv, eid;
    if (j < EE) { srcv = ei[j];       dstv = ei[EE + j]; eid = j; }
    else        { int e = j - EE; srcv = ei[EE + e]; dstv = ei[e]; eid = e; }
    int pos = atomicAdd(&g_cursor[dstv], 1);
    g_csrc[pos] = srcv;
    g_ceid[pos] = eid;
}

// ---------------- SGEMM 128x128x16, 256 thr, 8x8 microtile, f32x2 FMA, dbl-buffer --------
// epi: 0 = none, 2 = bias + PReLU(pa[0]), 3 = bias only
// If sOut != nullptr, fused per-row dot products with aS/aD (column tile == head).
__device__ __forceinline__ ull pack2(float a, float b) {
    ull r;
    asm("mov.b64 %0, {%1, %2};" : "=l"(r) : "f"(a), "f"(b));
    return r;
}
__device__ __forceinline__ void unpack2(ull v, float& lo, float& hi) {
    asm("mov.b64 {%0, %1}, %2;" : "=f"(lo), "=f"(hi) : "l"(v));
}
__device__ __forceinline__ void fma2(ull& acc, ull a, ull b) {
    asm("fma.rn.f32x2 %0, %1, %2, %0;" : "+l"(acc) : "l"(a), "l"(b));
}

__global__ __launch_bounds__(256) void sgemm_k(int M, int N, int K,
        const float* __restrict__ A, const float* __restrict__ B, float* __restrict__ C,
        const float* __restrict__ bias, const float* __restrict__ pa, int epi,
        const float* __restrict__ aS, const float* __restrict__ aD,
        float* __restrict__ sOut, float* __restrict__ dOut, int hs) {
    __shared__ float As[2][16][128];
    __shared__ float Bs[2][16][128];
    int tid = threadIdx.x;
    int rowBase = blockIdx.y * 128;
    int colBase = blockIdx.x * 128;
    int aRow = tid >> 1;
    int aCol = (tid & 1) * 8;
    int bRow = tid >> 4;            // 0..15
    int bCol = (tid & 15) * 8;
    int ty = tid >> 4, tx = tid & 15;
    ull acc[8][4];
    #pragma unroll
    for (int i = 0; i < 8; i++)
        #pragma unroll
        for (int j = 0; j < 4; j++) acc[i][j] = 0ull;

    // prologue: load chunk 0 into buf 0
    {
        int gr = rowBase + aRow;
        float4 a0 = make_float4(0.f, 0.f, 0.f, 0.f), a1 = a0;
        if (gr < M) {
            a0 = *reinterpret_cast<const float4*>(&A[(size_t)gr * K + aCol]);
            a1 = *reinterpret_cast<const float4*>(&A[(size_t)gr * K + aCol + 4]);
        }
        As[0][aCol + 0][aRow] = a0.x; As[0][aCol + 1][aRow] = a0.y;
        As[0][aCol + 2][aRow] = a0.z; As[0][aCol + 3][aRow] = a0.w;
        As[0][aCol + 4][aRow] = a1.x; As[0][aCol + 5][aRow] = a1.y;
        As[0][aCol + 6][aRow] = a1.z; As[0][aCol + 7][aRow] = a1.w;
        *reinterpret_cast<float4*>(&Bs[0][bRow][bCol]) =
            *reinterpret_cast<const float4*>(&B[(size_t)bRow * N + colBase + bCol]);
        *reinterpret_cast<float4*>(&Bs[0][bRow][bCol + 4]) =
            *reinterpret_cast<const float4*>(&B[(size_t)bRow * N + colBase + bCol + 4]);
    }
    __syncthreads();

    int nChunks = K >> 4;
    for (int ch = 0; ch < nChunks; ch++) {
        int buf = ch & 1;
        // prefetch next chunk into buf^1
        if (ch + 1 < nChunks) {
            int k0 = (ch + 1) << 4;
            int gr = rowBase + aRow;
            float4 a0 = make_float4(0.f, 0.f, 0.f, 0.f), a1 = a0;
            if (gr < M) {
                a0 = *reinterpret_cast<const float4*>(&A[(size_t)gr * K + k0 + aCol]);
                a1 = *reinterpret_cast<const float4*>(&A[(size_t)gr * K + k0 + aCol + 4]);
            }
            As[buf ^ 1][aCol + 0][aRow] = a0.x; As[buf ^ 1][aCol + 1][aRow] = a0.y;
            As[buf ^ 1][aCol + 2][aRow] = a0.z; As[buf ^ 1][aCol + 3][aRow] = a0.w;
            As[buf ^ 1][aCol + 4][aRow] = a1.x; As[buf ^ 1][aCol + 5][aRow] = a1.y;
            As[buf ^ 1][aCol + 6][aRow] = a1.z; As[buf ^ 1][aCol + 7][aRow] = a1.w;
            *reinterpret_cast<float4*>(&Bs[buf ^ 1][bRow][bCol]) =
                *reinterpret_cast<const float4*>(&B[(size_t)(k0 + bRow) * N + colBase + bCol]);
            *reinterpret_cast<float4*>(&Bs[buf ^ 1][bRow][bCol + 4]) =
                *reinterpret_cast<const float4*>(&B[(size_t)(k0 + bRow) * N + colBase + bCol + 4]);
        }
        // compute 16 kk-steps from buf
        #pragma unroll
        for (int kk = 0; kk < 16; kk++) {
            const float4* arp = reinterpret_cast<const float4*>(&As[buf][kk][ty * 8]);
            float4 a0 = arp[0], a1 = arp[1];
            ull ap[8];
            ap[0] = pack2(a0.x, a0.x); ap[1] = pack2(a0.y, a0.y);
            ap[2] = pack2(a0.z, a0.z); ap[3] = pack2(a0.w, a0.w);
            ap[4] = pack2(a1.x, a1.x); ap[5] = pack2(a1.y, a1.y);
            ap[6] = pack2(a1.z, a1.z); ap[7] = pack2(a1.w, a1.w);
            ull bp[4];
            const ull* brp = reinterpret_cast<const ull*>(&Bs[buf][kk][tx * 8]);
            bp[0] = brp[0]; bp[1] = brp[1]; bp[2] = brp[2]; bp[3] = brp[3];
            #pragma unroll
            for (int i = 0; i < 8; i++) {
                fma2(acc[i][0], ap[i], bp[0]);
                fma2(acc[i][1], ap[i], bp[1]);
                fma2(acc[i][2], ap[i], bp[2]);
                fma2(acc[i][3], ap[i], bp[3]);
            }
        }
        __syncthreads();
    }

    // unpack accumulators
    float accf[8][8];
    #pragma unroll
    for (int i = 0; i < 8; i++)
        #pragma unroll
        for (int j = 0; j < 4; j++)
            unpack2(acc[i][j], accf[i][2 * j], accf[i][2 * j + 1]);

    float pav = (epi == 2) ? pa[0] : 0.f;
    #pragma unroll
    for (int i = 0; i < 8; i++) {
        int r = rowBase + ty * 8 + i;
        if (r >= M) continue;
        #pragma unroll
        for (int j = 0; j < 8; j++) {
            int c = colBase + tx * 8 + j;
            float v = accf[i][j];
            if (epi) {
                v += bias[c];
                if (epi == 2) v = v > 0.f ? v : pav * v;
            }
            C[(size_t)r * N + c] = v;
        }
    }
    // fused attention dot products: s[r] = C_row . aS[head], d[r] = C_row . aD[head]
    if (sOut) {
        int head = colBase >> 7;
        float avr[8], dvr[8];
        #pragma unroll
        for (int j = 0; j < 8; j++) {
            avr[j] = aS[colBase + tx * 8 + j];
            dvr[j] = aD[colBase + tx * 8 + j];
        }
        #pragma unroll
        for (int i = 0; i < 8; i++) {
            float ps = 0.f, pd = 0.f;
            #pragma unroll
            for (int j = 0; j < 8; j++) { ps += accf[i][j] * avr[j]; pd += accf[i][j] * dvr[j]; }
            #pragma unroll
            for (int off = 8; off > 0; off >>= 1) {
                ps += __shfl_down_sync(0xffffffffu, ps, off, 16);
                pd += __shfl_down_sync(0xffffffffu, pd, off, 16);
            }
            if (tx == 0) {
                int r = rowBase + ty * 8 + i;
                if (r < M) { sOut[(size_t)r * hs + head] = ps; dOut[(size_t)r * hs + head] = pd; }
            }
        }
    }
}

// ---------------- layer-1 softmax weights: warp per node, 4 heads ----------------
__global__ __launch_bounds__(256) void wcalc1_k() {
    int n = blockIdx.x * 8 + (threadIdx.x >> 5);
    if (n >= NN) return;
    int lane = threadIdx.x & 31;
    int start = g_rowptr[n], end = g_rowptr[n + 1];
    if (start == end) return;
    float dl0 = g_d1[n * 4 + 0], dl1 = g_d1[n * 4 + 1];
    float dl2 = g_d1[n * 4 + 2], dl3 = g_d1[n * 4 + 3];
    float m0 = -INFINITY, m1 = -INFINITY, m2 = -INFINITY, m3 = -INFINITY;
    float s0 = 0.f, s1v = 0.f, s2v = 0.f, s3 = 0.f;
    for (int i = start + lane; i < end; i += 32) {
        int sr = g_csrc[i], e = g_ceid[i];
        float4 ap = g_aep1[e];
        float l0 = g_s1[sr * 4 + 0] + dl0 + ap.x; l0 = l0 > 0.f ? l0 : 0.2f * l0;
        float l1 = g_s1[sr * 4 + 1] + dl1 + ap.y; l1 = l1 > 0.f ? l1 : 0.2f * l1;
        float l2 = g_s1[sr * 4 + 2] + dl2 + ap.z; l2 = l2 > 0.f ? l2 : 0.2f * l2;
        float l3 = g_s1[sr * 4 + 3] + dl3 + ap.w; l3 = l3 > 0.f ? l3 : 0.2f * l3;
        g_w1[i] = make_float4(l0, l1, l2, l3);
        float nm;
        nm = fmaxf(m0, l0); s0  = s0  * __expf(m0 - nm) + __expf(l0 - nm); m0 = nm;
        nm = fmaxf(m1, l1); s1v = s1v * __expf(m1 - nm) + __expf(l1 - nm); m1 = nm;
        nm = fmaxf(m2, l2); s2v = s2v * __expf(m2 - nm) + __expf(l2 - nm); m2 = nm;
        nm = fmaxf(m3, l3); s3  = s3  * __expf(m3 - nm) + __expf(l3 - nm); m3 = nm;
    }
    #pragma unroll
    for (int off = 16; off > 0; off >>= 1) {
        float om, os, nm, a, b;
        om = __shfl_xor_sync(0xffffffffu, m0, off); os = __shfl_xor_sync(0xffffffffu, s0, off);
        nm = fmaxf(m0, om);
        a = (m0 == nm) ? s0 : s0 * __expf(m0 - nm);
        b = (om == nm) ? os : os * __expf(om - nm);
        s0 = a + b; m0 = nm;
        om = __shfl_xor_sync(0xffffffffu, m1, off); os = __shfl_xor_sync(0xffffffffu, s1v, off);
        nm = fmaxf(m1, om);
        a = (m1 == nm) ? s1v : s1v * __expf(m1 - nm);
        b = (om == nm) ? os : os * __expf(om - nm);
        s1v = a + b; m1 = nm;
        om = __shfl_xor_sync(0xffffffffu, m2, off); os = __shfl_xor_sync(0xffffffffu, s2v, off);
        nm = fmaxf(m2, om);
        a = (m2 == nm) ? s2v : s2v * __expf(m2 - nm);
        b = (om == nm) ? os : os * __expf(om - nm);
        s2v = a + b; m2 = nm;
        om = __shfl_xor_sync(0xffffffffu, m3, off); os = __shfl_xor_sync(0xffffffffu, s3, off);
        nm = fmaxf(m3, om);
        a = (m3 == nm) ? s3 : s3 * __expf(m3 - nm);
        b = (om == nm) ? os : os * __expf(om - nm);
        s3 = a + b; m3 = nm;
    }
    float i0 = 1.f / s0, i1 = 1.f / s1v, i2 = 1.f / s2v, i3 = 1.f / s3;
    for (int i = start + lane; i < end; i += 32) {
        float4 l = g_w1[i];
        g_w1[i] = make_float4(__expf(l.x - m0) * i0, __expf(l.y - m1) * i1,
                              __expf(l.z - m2) * i2, __expf(l.w - m3) * i3);
    }
}

// ---------------- layer-2 softmax weights: warp per node, 1 head ----------------
__global__ __launch_bounds__(256) void wcalc2_k() {
    int n = blockIdx.x * 8 + (threadIdx.x >> 5);
    if (n >= NN) return;
    int lane = threadIdx.x & 31;
    int start = g_rowptr[n], end = g_rowptr[n + 1];
    if (start == end) return;
    float dl = g_d2[n];
    float m = -INFINITY, s = 0.f;
    for (int i = start + lane; i < end; i += 32) {
        int sr = g_csrc[i], e = g_ceid[i];
        float l = g_s2[sr] + dl + g_aep2[e];
        l = l > 0.f ? l : 0.2f * l;
        g_w2[i] = l;
        float nm = fmaxf(m, l);
        s = s * __expf(m - nm) + __expf(l - nm);
        m = nm;
    }
    #pragma unroll
    for (int off = 16; off > 0; off >>= 1) {
        float om = __shfl_xor_sync(0xffffffffu, m, off);
        float os = __shfl_xor_sync(0xffffffffu, s, off);
        float nm = fmaxf(m, om);
        float a = (m == nm) ? s : s * __expf(m - nm);
        float b = (om == nm) ? os : os * __expf(om - nm);
        s = a + b; m = nm;
    }
    float inv = 1.f / s;
    for (int i = start + lane; i < end; i += 32)
        g_w2[i] = __expf(g_w2[i] - m) * inv;
}

// ---------------- layer-1 aggregation: pure weighted gather, 512 ch ----------------
__global__ __launch_bounds__(128) void agg1_k(const float* __restrict__ h1,
        const float* __restrict__ bias, float* __restrict__ out) {
    int n = blockIdx.x, tid = threadIdx.x;
    int start = g_rowptr[n], end = g_rowptr[n + 1];
    __shared__ int src_sh[128];
    __shared__ float4 w_sh[128];
    int hsel = tid >> 5;  // head index (warp-uniform)
    float4 acc = make_float4(0.f, 0.f, 0.f, 0.f);
    for (int t0 = start; t0 < end; t0 += 128) {
        int cnt = min(128, end - t0);
        if (tid < cnt) { src_sh[tid] = g_csrc[t0 + tid]; w_sh[tid] = g_w1[t0 + tid]; }
        __syncthreads();
        #pragma unroll 4
        for (int e = 0; e < cnt; e++) {
            int s = src_sh[e];
            float wv = reinterpret_cast<const float*>(&w_sh[e])[hsel];
            float4 hv = *reinterpret_cast<const float4*>(&h1[(size_t)s * D1 + tid * 4]);
            acc.x += hv.x * wv; acc.y += hv.y * wv; acc.z += hv.z * wv; acc.w += hv.w * wv;
        }
        __syncthreads();
    }
    const float4 bv = *reinterpret_cast<const float4*>(&bias[tid * 4]);
    float o0 = acc.x + bv.x, o1 = acc.y + bv.y, o2 = acc.z + bv.z, o3 = acc.w + bv.w;
    o0 = o0 > 0.f ? o0 : (__expf(o0) - 1.f);
    o1 = o1 > 0.f ? o1 : (__expf(o1) - 1.f);
    o2 = o2 > 0.f ? o2 : (__expf(o2) - 1.f);
    o3 = o3 > 0.f ? o3 : (__expf(o3) - 1.f);
    *reinterpret_cast<float4*>(&out[(size_t)n * D1 + tid * 4]) = make_float4(o0, o1, o2, o3);
}

// ---------------- layer-2 aggregation: warp per node, 128 ch ----------------
__global__ __launch_bounds__(256) void agg2_k(const float* __restrict__ h2t,
        const float* __restrict__ bias, float* __restrict__ out) {
    int n = blockIdx.x * 8 + (threadIdx.x >> 5);
    if (n >= NN) return;
    int lane = threadIdx.x & 31;
    int start = g_rowptr[n], end = g_rowptr[n + 1];
    float4 acc = make_float4(0.f, 0.f, 0.f, 0.f);
    for (int t0 = start; t0 < end; t0 += 32) {
        int cnt = min(32, end - t0);
        int sr = 0; float wv = 0.f;
        if (lane < cnt) { sr = g_csrc[t0 + lane]; wv = g_w2[t0 + lane]; }
        for (int j = 0; j < cnt; j++) {
            int s = __shfl_sync(0xffffffffu, sr, j);
            float w = __shfl_sync(0xffffffffu, wv, j);
            float4 hv = *reinterpret_cast<const float4*>(&h2t[(size_t)s * HID + lane * 4]);
            acc.x += hv.x * w; acc.y += hv.y * w; acc.z += hv.z * w; acc.w += hv.w * w;
        }
    }
    const float4 bv = *reinterpret_cast<const float4*>(&bias[lane * 4]);
    float o0 = acc.x + bv.x, o1 = acc.y + bv.y, o2 = acc.z + bv.z, o3 = acc.w + bv.w;
    o0 = o0 > 0.f ? o0 : (__expf(o0) - 1.f);
    o1 = o1 > 0.f ? o1 : (__expf(o1) - 1.f);
    o2 = o2 > 0.f ? o2 : (__expf(o2) - 1.f);
    o3 = o3 > 0.f ? o3 : (__expf(o3) - 1.f);
    *reinterpret_cast<float4*>(&out[(size_t)n * HID + lane * 4]) = make_float4(o0, o1, o2, o3);
}

// ---------------- column mean + sigmoid ----------------
__global__ void colsum_k(const float* __restrict__ hp) {
    int col = threadIdx.x;
    float acc = 0.f;
    for (int r = blockIdx.x; r < NN; r += gridDim.x) acc += hp[(size_t)r * HID + col];
    atomicAdd(&g_colsum[col], acc);
}

__global__ void final_k(float* __restrict__ outg) {
    int t = threadIdx.x;
    if (t < HID) {
        float m = g_colsum[t] / (float)NN;
        outg[t] = 1.f / (1.f + __expf(-m));
    }
}

// ---------------- launch ----------------
extern "C" void kernel_launch(void* const* d_in, const int* in_sizes, int n_in,
                              void* d_out, int out_size) {
    const float* x   = (const float*)d_in[0];
    const int*   ei  = (const int*)  d_in[1];
    const float* ea  = (const float*)d_in[2];
    const float* W1  = (const float*)d_in[3];
    const float* We1 = (const float*)d_in[4];
    const float* as1 = (const float*)d_in[5];
    const float* ad1 = (const float*)d_in[6];
    const float* ae1 = (const float*)d_in[7];
    const float* b1  = (const float*)d_in[8];
    const float* W2  = (const float*)d_in[9];
    const float* We2 = (const float*)d_in[10];
    const float* as2 = (const float*)d_in[11];
    const float* ad2 = (const float*)d_in[12];
    const float* ae2 = (const float*)d_in[13];
    const float* b2  = (const float*)d_in[14];
    const float* P1  = (const float*)d_in[15];
    const float* pb1 = (const float*)d_in[16];
    const float* pa  = (const float*)d_in[17];
    const float* P2  = (const float*)d_in[18];
    const float* pb2 = (const float*)d_in[19];
    float* out = (float*)d_out;

    float *p_h1, *p_out1, *p_h2t, *p_h2, *p_z, *p_s1, *p_d1, *p_s2, *p_d2;
    cudaGetSymbolAddress((void**)&p_h1,   g_h1);
    cudaGetSymbolAddress((void**)&p_out1, g_out1);
    cudaGetSymbolAddress((void**)&p_h2t,  g_h2t);
    cudaGetSymbolAddress((void**)&p_h2,   g_h2);
    cudaGetSymbolAddress((void**)&p_z,    g_z);
    cudaGetSymbolAddress((void**)&p_s1,   g_s1);
    cudaGetSymbolAddress((void**)&p_d1,   g_d1);
    cudaGetSymbolAddress((void**)&p_s2,   g_s2);
    cudaGetSymbolAddress((void**)&p_d2,   g_d2);

    zero_k<<<(NN + 255) / 256, 256>>>();
    wev_k<<<1, FE * HEADS + FE>>>(We1, ae1, We2, ae2);
    aeproj_k<<<(EE + 7) / 8, 256>>>(ea);
    hist_k<<<(E2 + 255) / 256, 256>>>(ei);
    scan_k<<<1, 1024>>>();
    fill_k<<<(E2 + 255) / 256, 256>>>(ei);

    // layer 1: GEMM with fused attention dots
    sgemm_k<<<dim3(D1 / 128, (NN + 127) / 128), 256>>>(NN, D1, FIN, x, W1, p_h1,
            nullptr, nullptr, 0, as1, ad1, p_s1, p_d1, HEADS);
    wcalc1_k<<<(NN + 7) / 8, 256>>>();
    agg1_k<<<NN, 128>>>(p_h1, b1, p_out1);

    // layer 2
    sgemm_k<<<dim3(1, (NN + 127) / 128), 256>>>(NN, HID, D1, p_out1, W2, p_h2t,
            nullptr, nullptr, 0, as2, ad2, p_s2, p_d2, 1);
    wcalc2_k<<<(NN + 7) / 8, 256>>>();
    agg2_k<<<(NN + 7) / 8, 256>>>(p_h2t, b2, p_h2);

    // projection head
    sgemm_k<<<dim3(1, (NN + 127) / 128), 256>>>(NN, HID, HID, p_h2, P1, p_z,
            pb1, pa, 2, nullptr, nullptr, nullptr, nullptr, 1);
    sgemm_k<<<dim3(1, (NN + 127) / 128), 256>>>(NN, HID, HID, p_z, P2, out,
            pb2, nullptr, 3, nullptr, nullptr, nullptr, nullptr, 1);

    // g = sigmoid(mean(h_proj, axis=0))
    colsum_k<<<128, 128>>>(out);
    final_k<<<1, 128>>>(out + (size_t)NN * HID);
}

// round 5
// speedup vs baseline: 1.2088x; 1.0016x over previous
#include <cuda_runtime.h>
#include <cuda_bf16.h>
#include <math.h>
#include <stdint.h>

// ---------------- problem constants ----------------
constexpr int NN   = 20000;    // nodes
constexpr int EE   = 320000;   // edges (before doubling)
constexpr int E2   = 2 * EE;   // doubled edges
constexpr int FIN  = 256;
constexpr int FE   = 32;
constexpr int HID  = 128;
constexpr int HEADS = 4;
constexpr int D1   = HEADS * HID; // 512

typedef unsigned long long ull;

// ---------------- device scratch (static, no allocs) ----------------
__device__ __align__(16) float g_h1   [(size_t)NN * D1];   // x@W1
__device__ __align__(16) float g_out1 [(size_t)NN * D1];   // layer1 output (post ELU)
__device__ __align__(16) float g_h2t  [(size_t)NN * HID];  // h@W2
__device__ __align__(16) float g_h2   [(size_t)NN * HID];  // layer2 output (post ELU)
__device__ __align__(16) float g_z    [(size_t)NN * HID];  // proj1 output (post PReLU)
__device__ __align__(16) float g_s1   [NN * HEADS];
__device__ __align__(16) float g_d1   [NN * HEADS];
__device__ float g_s2   [NN];
__device__ float g_d2   [NN];
__device__ float4 g_aep1 [EE];     // per-edge logit contribution, 4 heads
__device__ float  g_aep2 [EE];
__device__ float4 g_w1   [E2];     // per-CSR-slot: logits then normalized weights (4 heads)
__device__ float  g_w2   [E2];     // layer-2 weights per CSR slot
__device__ float g_wev1 [FE * HEADS];
__device__ float g_wev2 [FE];
__device__ int   g_deg  [NN];
__device__ int   g_rowptr[NN + 1];
__device__ int   g_cursor[NN];
__device__ int   g_csrc [E2];
__device__ int   g_ceid [E2];
__device__ float g_colsum[HID];

// ---------------- small helpers ----------------
__global__ void zero_k() {
    int i = blockIdx.x * blockDim.x + threadIdx.x;
    if (i < NN) g_deg[i] = 0;
    if (i < HID) g_colsum[i] = 0.f;
}

// wev1[f*4+h] = sum_c We1[f,h*128+c]*ae1[h,c];  wev2[f] = sum_c We2[f,c]*ae2[c]
__global__ void wev_k(const float* __restrict__ We1, const float* __restrict__ ae1,
                      const float* __restrict__ We2, const float* __restrict__ ae2) {
    int t = threadIdx.x;
    if (t < FE * HEADS) {
        int f = t >> 2, h = t & 3;
        float s = 0.f;
        for (int c = 0; c < HID; c++) s += We1[(size_t)f * D1 + h * HID + c] * ae1[h * HID + c];
        g_wev1[t] = s;
    } else if (t < FE * HEADS + FE) {
        int f = t - FE * HEADS;
        float s = 0.f;
        for (int c = 0; c < HID; c++) s += We2[(size_t)f * HID + c] * ae2[c];
        g_wev2[f] = s;
    }
}

// per-edge logit contributions: aep1[e][h] = ea[e,:] . wev1[:,h]; aep2[e] = ea[e,:] . wev2
__global__ __launch_bounds__(256) void aeproj_k(const float* __restrict__ ea) {
    __shared__ float w1s[FE * HEADS];
    __shared__ float w2s[FE];
    int tid = threadIdx.x;
    if (tid < FE * HEADS) w1s[tid] = g_wev1[tid];
    if (tid < FE)         w2s[tid] = g_wev2[tid];
    __syncthreads();
    int e = blockIdx.x * 8 + (tid >> 5);
    int lane = tid & 31;
    if (e >= EE) return;
    float v = ea[(size_t)e * FE + lane];
    float p0 = v * w1s[lane * 4 + 0];
    float p1 = v * w1s[lane * 4 + 1];
    float p2 = v * w1s[lane * 4 + 2];
    float p3 = v * w1s[lane * 4 + 3];
    float p4 = v * w2s[lane];
    #pragma unroll
    for (int off = 16; off > 0; off >>= 1) {
        p0 += __shfl_down_sync(0xffffffffu, p0, off);
        p1 += __shfl_down_sync(0xffffffffu, p1, off);
        p2 += __shfl_down_sync(0xffffffffu, p2, off);
        p3 += __shfl_down_sync(0xffffffffu, p3, off);
        p4 += __shfl_down_sync(0xffffffffu, p4, off);
    }
    if (lane == 0) {
        g_aep1[e] = make_float4(p0, p1, p2, p3);
        g_aep2[e] = p4;
    }
}

// ---------------- CSR build (by destination) ----------------
__global__ void hist_k(const int* __restrict__ ei) {
    int j = blockIdx.x * blockDim.x + threadIdx.x;
    if (j >= E2) return;
    int dst = (j < EE) ? ei[EE + j] : ei[j - EE];
    atomicAdd(&g_deg[dst], 1);
}

__global__ __launch_bounds__(1024) void scan_k() {
    __shared__ int part[1024];
    int tid = threadIdx.x;
    const int CH = (NN + 1023) / 1024;
    int base = tid * CH;
    int s = 0;
    for (int i = 0; i < CH; i++) {
        int idx = base + i;
        if (idx < NN) s += g_deg[idx];
    }
    part[tid] = s;
    __syncthreads();
    for (int off = 1; off < 1024; off <<= 1) {
        int v = (tid >= off) ? part[tid - off] : 0;
        __syncthreads();
        part[tid] += v;
        __syncthreads();
    }
    int pre = part[tid] - s; // exclusive prefix
    for (int i = 0; i < CH; i++) {
        int idx = base + i;
        if (idx < NN) {
            g_rowptr[idx] = pre;
            g_cursor[idx] = pre;
            pre += g_deg[idx];
        }
    }
    if (tid == 1023) g_rowptr[NN] = part[1023];
}

__global__ void fill_k(const int* __restrict__ ei) {
    int j = blockIdx.x * blockDim.x + threadIdx.x;
    if (j >= E2) return;
    int srcv, dstv, eid;
    if (j < EE) { srcv = ei[j];       dstv = ei[EE + j]; eid = j; }
    else        { int e = j - EE; srcv = ei[EE + e]; dstv = ei[e]; eid = e; }
    int pos = atomicAdd(&g_cursor[dstv], 1);
    g_csrc[pos] = srcv;
    g_ceid[pos] = eid;
}

// ---------------- SGEMM 128x128x16, 256 thr, 8x8 microtile, f32x2 FMA, dbl-buffer --------
// epi: 0 = none, 2 = bias + PReLU(pa[0]), 3 = bias only
// If sOut != nullptr, fused per-row dot products with aS/aD (column tile == head).
__device__ __forceinline__ ull pack2(float a, float b) {
    ull r;
    asm("mov.b64 %0, {%1, %2};" : "=l"(r) : "f"(a), "f"(b));
    return r;
}
__device__ __forceinline__ void unpack2(ull v, float& lo, float& hi) {
    asm("mov.b64 {%0, %1}, %2;" : "=f"(lo), "=f"(hi) : "l"(v));
}
__device__ __forceinline__ void fma2(ull& acc, ull a, ull b) {
    asm("fma.rn.f32x2 %0, %1, %2, %0;" : "+l"(acc) : "l"(a), "l"(b));
}

__global__ __launch_bounds__(256) void sgemm_k(int M, int N, int K,
        const float* __restrict__ A, const float* __restrict__ B, float* __restrict__ C,
        const float* __restrict__ bias, const float* __restrict__ pa, int epi,
        const float* __restrict__ aS, const float* __restrict__ aD,
        float* __restrict__ sOut, float* __restrict__ dOut, int hs) {
    __shared__ float As[2][16][128];
    __shared__ float Bs[2][16][128];
    int tid = threadIdx.x;
    int rowBase = blockIdx.y * 128;
    int colBase = blockIdx.x * 128;
    int aRow = tid >> 1;
    int aCol = (tid & 1) * 8;
    int bRow = tid >> 4;            // 0..15
    int bCol = (tid & 15) * 8;
    int ty = tid >> 4, tx = tid & 15;
    ull acc[8][4];
    #pragma unroll
    for (int i = 0; i < 8; i++)
        #pragma unroll
        for (int j = 0; j < 4; j++) acc[i][j] = 0ull;

    // prologue: load chunk 0 into buf 0
    {
        int gr = rowBase + aRow;
        float4 a0 = make_float4(0.f, 0.f, 0.f, 0.f), a1 = a0;
        if (gr < M) {
            a0 = *reinterpret_cast<const float4*>(&A[(size_t)gr * K + aCol]);
            a1 = *reinterpret_cast<const float4*>(&A[(size_t)gr * K + aCol + 4]);
        }
        As[0][aCol + 0][aRow] = a0.x; As[0][aCol + 1][aRow] = a0.y;
        As[0][aCol + 2][aRow] = a0.z; As[0][aCol + 3][aRow] = a0.w;
        As[0][aCol + 4][aRow] = a1.x; As[0][aCol + 5][aRow] = a1.y;
        As[0][aCol + 6][aRow] = a1.z; As[0][aCol + 7][aRow] = a1.w;
        *reinterpret_cast<float4*>(&Bs[0][bRow][bCol]) =
            *reinterpret_cast<const float4*>(&B[(size_t)bRow * N + colBase + bCol]);
        *reinterpret_cast<float4*>(&Bs[0][bRow][bCol + 4]) =
            *reinterpret_cast<const float4*>(&B[(size_t)bRow * N + colBase + bCol + 4]);
    }
    __syncthreads();

    int nChunks = K >> 4;
    for (int ch = 0; ch < nChunks; ch++) {
        int buf = ch & 1;
        // prefetch next chunk into buf^1
        if (ch + 1 < nChunks) {
            int k0 = (ch + 1) << 4;
            int gr = rowBase + aRow;
            float4 a0 = make_float4(0.f, 0.f, 0.f, 0.f), a1 = a0;
            if (gr < M) {
                a0 = *reinterpret_cast<const float4*>(&A[(size_t)gr * K + k0 + aCol]);
                a1 = *reinterpret_cast<const float4*>(&A[(size_t)gr * K + k0 + aCol + 4]);
            }
            As[buf ^ 1][aCol + 0][aRow] = a0.x; As[buf ^ 1][aCol + 1][aRow] = a0.y;
            As[buf ^ 1][aCol + 2][aRow] = a0.z; As[buf ^ 1][aCol + 3][aRow] = a0.w;
            As[buf ^ 1][aCol + 4][aRow] = a1.x; As[buf ^ 1][aCol + 5][aRow] = a1.y;
            As[buf ^ 1][aCol + 6][aRow] = a1.z; As[buf ^ 1][aCol + 7][aRow] = a1.w;
            *reinterpret_cast<float4*>(&Bs[buf ^ 1][bRow][bCol]) =
                *reinterpret_cast<const float4*>(&B[(size_t)(k0 + bRow) * N + colBase + bCol]);
            *reinterpret_cast<float4*>(&Bs[buf ^ 1][bRow][bCol + 4]) =
                *reinterpret_cast<const float4*>(&B[(size_t)(k0 + bRow) * N + colBase + bCol + 4]);
        }
        // compute 16 kk-steps from buf
        #pragma unroll
        for (int kk = 0; kk < 16; kk++) {
            const float4* arp = reinterpret_cast<const float4*>(&As[buf][kk][ty * 8]);
            float4 a0 = arp[0], a1 = arp[1];
            ull ap[8];
            ap[0] = pack2(a0.x, a0.x); ap[1] = pack2(a0.y, a0.y);
            ap[2] = pack2(a0.z, a0.z); ap[3] = pack2(a0.w, a0.w);
            ap[4] = pack2(a1.x, a1.x); ap[5] = pack2(a1.y, a1.y);
            ap[6] = pack2(a1.z, a1.z); ap[7] = pack2(a1.w, a1.w);
            ull bp[4];
            const ull* brp = reinterpret_cast<const ull*>(&Bs[buf][kk][tx * 8]);
            bp[0] = brp[0]; bp[1] = brp[1]; bp[2] = brp[2]; bp[3] = brp[3];
            #pragma unroll
            for (int i = 0; i < 8; i++) {
                fma2(acc[i][0], ap[i], bp[0]);
                fma2(acc[i][1], ap[i], bp[1]);
                fma2(acc[i][2], ap[i], bp[2]);
                fma2(acc[i][3], ap[i], bp[3]);
            }
        }
        __syncthreads();
    }

    // unpack accumulators
    float accf[8][8];
    #pragma unroll
    for (int i = 0; i < 8; i++)
        #pragma unroll
        for (int j = 0; j < 4; j++)
            unpack2(acc[i][j], accf[i][2 * j], accf[i][2 * j + 1]);

    float pav = (epi == 2) ? pa[0] : 0.f;
    #pragma unroll
    for (int i = 0; i < 8; i++) {
        int r = rowBase + ty * 8 + i;
        if (r >= M) continue;
        #pragma unroll
        for (int j = 0; j < 8; j++) {
            int c = colBase + tx * 8 + j;
            float v = accf[i][j];
            if (epi) {
                v += bias[c];
                if (epi == 2) v = v > 0.f ? v : pav * v;
            }
            C[(size_t)r * N + c] = v;
        }
    }
    // fused attention dot products: s[r] = C_row . aS[head], d[r] = C_row . aD[head]
    if (sOut) {
        int head = colBase >> 7;
        float avr[8], dvr[8];
        #pragma unroll
        for (int j = 0; j < 8; j++) {
            avr[j] = aS[colBase + tx * 8 + j];
            dvr[j] = aD[colBase + tx * 8 + j];
        }
        #pragma unroll
        for (int i = 0; i < 8; i++) {
            float ps = 0.f, pd = 0.f;
            #pragma unroll
            for (int j = 0; j < 8; j++) { ps += accf[i][j] * avr[j]; pd += accf[i][j] * dvr[j]; }
            #pragma unroll
            for (int off = 8; off > 0; off >>= 1) {
                ps += __shfl_down_sync(0xffffffffu, ps, off, 16);
                pd += __shfl_down_sync(0xffffffffu, pd, off, 16);
            }
            if (tx == 0) {
                int r = rowBase + ty * 8 + i;
                if (r < M) { sOut[(size_t)r * hs + head] = ps; dOut[(size_t)r * hs + head] = pd; }
            }
        }
    }
}

// ---------------- layer-1 softmax weights: warp per node, 4 heads ----------------
__global__ __launch_bounds__(256) void wcalc1_k() {
    int n = blockIdx.x * 8 + (threadIdx.x >> 5);
    if (n >= NN) return;
    int lane = threadIdx.x & 31;
    int start = g_rowptr[n], end = g_rowptr[n + 1];
    if (start == end) return;
    float dl0 = g_d1[n * 4 + 0], dl1 = g_d1[n * 4 + 1];
    float dl2 = g_d1[n * 4 + 2], dl3 = g_d1[n * 4 + 3];
    float m0 = -INFINITY, m1 = -INFINITY, m2 = -INFINITY, m3 = -INFINITY;
    float s0 = 0.f, s1v = 0.f, s2v = 0.f, s3 = 0.f;
    for (int i = start + lane; i < end; i += 32) {
        int sr = g_csrc[i], e = g_ceid[i];
        float4 ap = g_aep1[e];
        float l0 = g_s1[sr * 4 + 0] + dl0 + ap.x; l0 = l0 > 0.f ? l0 : 0.2f * l0;
        float l1 = g_s1[sr * 4 + 1] + dl1 + ap.y; l1 = l1 > 0.f ? l1 : 0.2f * l1;
        float l2 = g_s1[sr * 4 + 2] + dl2 + ap.z; l2 = l2 > 0.f ? l2 : 0.2f * l2;
        float l3 = g_s1[sr * 4 + 3] + dl3 + ap.w; l3 = l3 > 0.f ? l3 : 0.2f * l3;
        g_w1[i] = make_float4(l0, l1, l2, l3);
        float nm;
        nm = fmaxf(m0, l0); s0  = s0  * __expf(m0 - nm) + __expf(l0 - nm); m0 = nm;
        nm = fmaxf(m1, l1); s1v = s1v * __expf(m1 - nm) + __expf(l1 - nm); m1 = nm;
        nm = fmaxf(m2, l2); s2v = s2v * __expf(m2 - nm) + __expf(l2 - nm); m2 = nm;
        nm = fmaxf(m3, l3); s3  = s3  * __expf(m3 - nm) + __expf(l3 - nm); m3 = nm;
    }
    #pragma unroll
    for (int off = 16; off > 0; off >>= 1) {
        float om, os, nm, a, b;
        om = __shfl_xor_sync(0xffffffffu, m0, off); os = __shfl_xor_sync(0xffffffffu, s0, off);
        nm = fmaxf(m0, om);
        a = (m0 == nm) ? s0 : s0 * __expf(m0 - nm);
        b = (om == nm) ? os : os * __expf(om - nm);
        s0 = a + b; m0 = nm;
        om = __shfl_xor_sync(0xffffffffu, m1, off); os = __shfl_xor_sync(0xffffffffu, s1v, off);
        nm = fmaxf(m1, om);
        a = (m1 == nm) ? s1v : s1v * __expf(m1 - nm);
        b = (om == nm) ? os : os * __expf(om - nm);
        s1v = a + b; m1 = nm;
        om = __shfl_xor_sync(0xffffffffu, m2, off); os = __shfl_xor_sync(0xffffffffu, s2v, off);
        nm = fmaxf(m2, om);
        a = (m2 == nm) ? s2v : s2v * __expf(m2 - nm);
        b = (om == nm) ? os : os * __expf(om - nm);
        s2v = a + b; m2 = nm;
        om = __shfl_xor_sync(0xffffffffu, m3, off); os = __shfl_xor_sync(0xffffffffu, s3, off);
        nm = fmaxf(m3, om);
        a = (m3 == nm) ? s3 : s3 * __expf(m3 - nm);
        b = (om == nm) ? os : os * __expf(om - nm);
        s3 = a + b; m3 = nm;
    }
    float i0 = 1.f / s0, i1 = 1.f / s1v, i2 = 1.f / s2v, i3 = 1.f / s3;
    for (int i = start + lane; i < end; i += 32) {
        float4 l = g_w1[i];
        g_w1[i] = make_float4(__expf(l.x - m0) * i0, __expf(l.y - m1) * i1,
                              __expf(l.z - m2) * i2, __expf(l.w - m3) * i3);
    }
}

// ---------------- layer-2 softmax weights: warp per node, 1 head ----------------
__global__ __launch_bounds__(256) void wcalc2_k() {
    int n = blockIdx.x * 8 + (threadIdx.x >> 5);
    if (n >= NN) return;
    int lane = threadIdx.x & 31;
    int start = g_rowptr[n], end = g_rowptr[n + 1];
    if (start == end) return;
    float dl = g_d2[n];
    float m = -INFINITY, s = 0.f;
    for (int i = start + lane; i < end; i += 32) {
        int sr = g_csrc[i], e = g_ceid[i];
        float l = g_s2[sr] + dl + g_aep2[e];
        l = l > 0.f ? l : 0.2f * l;
        g_w2[i] = l;
        float nm = fmaxf(m, l);
        s = s * __expf(m - nm) + __expf(l - nm);
        m = nm;
    }
    #pragma unroll
    for (int off = 16; off > 0; off >>= 1) {
        float om = __shfl_xor_sync(0xffffffffu, m, off);
        float os = __shfl_xor_sync(0xffffffffu, s, off);
        float nm = fmaxf(m, om);
        float a = (m == nm) ? s : s * __expf(m - nm);
        float b = (om == nm) ? os : os * __expf(om - nm);
        s = a + b; m = nm;
    }
    float inv = 1.f / s;
    for (int i = start + lane; i < end; i += 32)
        g_w2[i] = __expf(g_w2[i] - m) * inv;
}

// ---------------- layer-1 aggregation: pure weighted gather, 512 ch ----------------
__global__ __launch_bounds__(128) void agg1_k(const float* __restrict__ h1,
        const float* __restrict__ bias, float* __restrict__ out) {
    int n = blockIdx.x, tid = threadIdx.x;
    int start = g_rowptr[n], end = g_rowptr[n + 1];
    __shared__ int src_sh[128];
    __shared__ float4 w_sh[128];
    int hsel = tid >> 5;  // head index (warp-uniform)
    float4 acc = make_float4(0.f, 0.f, 0.f, 0.f);
    for (int t0 = start; t0 < end; t0 += 128) {
        int cnt = min(128, end - t0);
        if (tid < cnt) { src_sh[tid] = g_csrc[t0 + tid]; w_sh[tid] = g_w1[t0 + tid]; }
        __syncthreads();
        #pragma unroll 4
        for (int e = 0; e < cnt; e++) {
            int s = src_sh[e];
            float wv = reinterpret_cast<const float*>(&w_sh[e])[hsel];
            float4 hv = *reinterpret_cast<const float4*>(&h1[(size_t)s * D1 + tid * 4]);
            acc.x += hv.x * wv; acc.y += hv.y * wv; acc.z += hv.z * wv; acc.w += hv.w * wv;
        }
        __syncthreads();
    }
    const float4 bv = *reinterpret_cast<const float4*>(&bias[tid * 4]);
    float o0 = acc.x + bv.x, o1 = acc.y + bv.y, o2 = acc.z + bv.z, o3 = acc.w + bv.w;
    o0 = o0 > 0.f ? o0 : (__expf(o0) - 1.f);
    o1 = o1 > 0.f ? o1 : (__expf(o1) - 1.f);
    o2 = o2 > 0.f ? o2 : (__expf(o2) - 1.f);
    o3 = o3 > 0.f ? o3 : (__expf(o3) - 1.f);
    *reinterpret_cast<float4*>(&out[(size_t)n * D1 + tid * 4]) = make_float4(o0, o1, o2, o3);
}

// ---------------- layer-2 aggregation: warp per node, 128 ch ----------------
__global__ __launch_bounds__(256) void agg2_k(const float* __restrict__ h2t,
        const float* __restrict__ bias, float* __restrict__ out) {
    int n = blockIdx.x * 8 + (threadIdx.x >> 5);
    if (n >= NN) return;
    int lane = threadIdx.x & 31;
    int start = g_rowptr[n], end = g_rowptr[n + 1];
    float4 acc = make_float4(0.f, 0.f, 0.f, 0.f);
    for (int t0 = start; t0 < end; t0 += 32) {
        int cnt = min(32, end - t0);
        int sr = 0; float wv = 0.f;
        if (lane < cnt) { sr = g_csrc[t0 + lane]; wv = g_w2[t0 + lane]; }
        for (int j = 0; j < cnt; j++) {
            int s = __shfl_sync(0xffffffffu, sr, j);
            float w = __shfl_sync(0xffffffffu, wv, j);
            float4 hv = *reinterpret_cast<const float4*>(&h2t[(size_t)s * HID + lane * 4]);
            acc.x += hv.x * w; acc.y += hv.y * w; acc.z += hv.z * w; acc.w += hv.w * w;
        }
    }
    const float4 bv = *reinterpret_cast<const float4*>(&bias[lane * 4]);
    float o0 = acc.x + bv.x, o1 = acc.y + bv.y, o2 = acc.z + bv.z, o3 = acc.w + bv.w;
    o0 = o0 > 0.f ? o0 : (__expf(o0) - 1.f);
    o1 = o1 > 0.f ? o1 : (__expf(o1) - 1.f);
    o2 = o2 > 0.f ? o2 : (__expf(o2) - 1.f);
    o3 = o3 > 0.f ? o3 : (__expf(o3) - 1.f);
    *reinterpret_cast<float4*>(&out[(size_t)n * HID + lane * 4]) = make_float4(o0, o1, o2, o3);
}

// ---------------- column mean + sigmoid ----------------
__global__ void colsum_k(const float* __restrict__ hp) {
    int col = threadIdx.x;
    float acc = 0.f;
    for (int r = blockIdx.x; r < NN; r += gridDim.x) acc += hp[(size_t)r * HID + col];
    atomicAdd(&g_colsum[col], acc);
}

__global__ void final_k(float* __restrict__ outg) {
    int t = threadIdx.x;
    if (t < HID) {
        float m = g_colsum[t] / (float)NN;
        outg[t] = 1.f / (1.f + __expf(-m));
    }
}

// ---------------- launch ----------------
extern "C" void kernel_launch(void* const* d_in, const int* in_sizes, int n_in,
                              void* d_out, int out_size) {
    const float* x   = (const float*)d_in[0];
    const int*   ei  = (const int*)  d_in[1];
    const float* ea  = (const float*)d_in[2];
    const float* W1  = (const float*)d_in[3];
    const float* We1 = (const float*)d_in[4];
    const float* as1 = (const float*)d_in[5];
    const float* ad1 = (const float*)d_in[6];
    const float* ae1 = (const float*)d_in[7];
    const float* b1  = (const float*)d_in[8];
    const float* W2  = (const float*)d_in[9];
    const float* We2 = (const float*)d_in[10];
    const float* as2 = (const float*)d_in[11];
    const float* ad2 = (const float*)d_in[12];
    const float* ae2 = (const float*)d_in[13];
    const float* b2  = (const float*)d_in[14];
    const float* P1  = (const float*)d_in[15];
    const float* pb1 = (const float*)d_in[16];
    const float* pa  = (const float*)d_in[17];
    const float* P2  = (const float*)d_in[18];
    const float* pb2 = (const float*)d_in[19];
    float* out = (float*)d_out;

    float *p_h1, *p_out1, *p_h2t, *p_h2, *p_z, *p_s1, *p_d1, *p_s2, *p_d2;
    cudaGetSymbolAddress((void**)&p_h1,   g_h1);
    cudaGetSymbolAddress((void**)&p_out1, g_out1);
    cudaGetSymbolAddress((void**)&p_h2t,  g_h2t);
    cudaGetSymbolAddress((void**)&p_h2,   g_h2);
    cudaGetSymbolAddress((void**)&p_z,    g_z);
    cudaGetSymbolAddress((void**)&p_s1,   g_s1);
    cudaGetSymbolAddress((void**)&p_d1,   g_d1);
    cudaGetSymbolAddress((void**)&p_s2,   g_s2);
    cudaGetSymbolAddress((void**)&p_d2,   g_d2);

    zero_k<<<(NN + 255) / 256, 256>>>();
    wev_k<<<1, FE * HEADS + FE>>>(We1, ae1, We2, ae2);
    aeproj_k<<<(EE + 7) / 8, 256>>>(ea);
    hist_k<<<(E2 + 255) / 256, 256>>>(ei);
    scan_k<<<1, 1024>>>();
    fill_k<<<(E2 + 255) / 256, 256>>>(ei);

    // layer 1: GEMM with fused attention dots
    sgemm_k<<<dim3(D1 / 128, (NN + 127) / 128), 256>>>(NN, D1, FIN, x, W1, p_h1,
            nullptr, nullptr, 0, as1, ad1, p_s1, p_d1, HEADS);
    wcalc1_k<<<(NN + 7) / 8, 256>>>();
    agg1_k<<<NN, 128>>>(p_h1, b1, p_out1);

    // layer 2
    sgemm_k<<<dim3(1, (NN + 127) / 128), 256>>>(NN, HID, D1, p_out1, W2, p_h2t,
            nullptr, nullptr, 0, as2, ad2, p_s2, p_d2, 1);
    wcalc2_k<<<(NN + 7) / 8, 256>>>();
    agg2_k<<<(NN + 7) / 8, 256>>>(p_h2t, b2, p_h2);

    // projection head
    sgemm_k<<<dim3(1, (NN + 127) / 128), 256>>>(NN, HID, HID, p_h2, P1, p_z,
            pb1, pa, 2, nullptr, nullptr, nullptr, nullptr, 1);
    sgemm_k<<<dim3(1, (NN + 127) / 128), 256>>>(NN, HID, HID, p_z, P2, out,
            pb2, nullptr, 3, nullptr, nullptr, nullptr, nullptr, 1);

    // g = sigmoid(mean(h_proj, axis=0))
    colsum_k<<<128, 128>>>(out);
    final_k<<<1, 128>>>(out + (size_t)NN * HID);
}

// round 6
// speedup vs baseline: 1.2116x; 1.0023x over previous
#include <cuda_runtime.h>
#include <cuda_bf16.h>
#include <math.h>
#include <stdint.h>

// ---------------- problem constants ----------------
constexpr int NN   = 20000;    // nodes
constexpr int EE   = 320000;   // edges (before doubling)
constexpr int E2   = 2 * EE;   // doubled edges
constexpr int FIN  = 256;
constexpr int FE   = 32;
constexpr int HID  = 128;
constexpr int HEADS = 4;
constexpr int D1   = HEADS * HID; // 512

typedef unsigned long long ull;

// ---------------- device scratch (static, no allocs) ----------------
__device__ __align__(16) float g_h1   [(size_t)NN * D1];   // x@W1
__device__ __align__(16) float g_out1 [(size_t)NN * D1];   // layer1 output (post ELU)
__device__ __align__(16) float g_h2t  [(size_t)NN * HID];  // h@W2
__device__ __align__(16) float g_h2   [(size_t)NN * HID];  // layer2 output (post ELU)
__device__ __align__(16) float g_z    [(size_t)NN * HID];  // proj1 output (post PReLU)
__device__ __align__(16) float g_s1   [NN * HEADS];
__device__ __align__(16) float g_d1   [NN * HEADS];
__device__ float g_s2   [NN];
__device__ float g_d2   [NN];
__device__ float4 g_aep1 [EE];     // per-edge logit contribution, 4 heads
__device__ float  g_aep2 [EE];
__device__ float4 g_w1   [E2];     // per-CSR-slot: logits then normalized weights (4 heads)
__device__ float  g_w2   [E2];     // layer-2 weights per CSR slot
__device__ float g_wev1 [FE * HEADS];
__device__ float g_wev2 [FE];
__device__ int   g_deg  [NN];
__device__ int   g_rowptr[NN + 1];
__device__ int   g_cursor[NN];
__device__ int   g_csrc [E2];
__device__ int   g_ceid [E2];
__device__ float g_colsum[HID];

// ---------------- small helpers ----------------
__global__ void zero_k() {
    int i = blockIdx.x * blockDim.x + threadIdx.x;
    if (i < NN) g_deg[i] = 0;
    if (i < HID) g_colsum[i] = 0.f;
}

// wev1[f*4+h] = sum_c We1[f,h*128+c]*ae1[h,c];  wev2[f] = sum_c We2[f,c]*ae2[c]
__global__ void wev_k(const float* __restrict__ We1, const float* __restrict__ ae1,
                      const float* __restrict__ We2, const float* __restrict__ ae2) {
    int t = threadIdx.x;
    if (t < FE * HEADS) {
        int f = t >> 2, h = t & 3;
        float s = 0.f;
        for (int c = 0; c < HID; c++) s += We1[(size_t)f * D1 + h * HID + c] * ae1[h * HID + c];
        g_wev1[t] = s;
    } else if (t < FE * HEADS + FE) {
        int f = t - FE * HEADS;
        float s = 0.f;
        for (int c = 0; c < HID; c++) s += We2[(size_t)f * HID + c] * ae2[c];
        g_wev2[f] = s;
    }
}

// per-edge logit contributions: aep1[e][h] = ea[e,:] . wev1[:,h]; aep2[e] = ea[e,:] . wev2
__global__ __launch_bounds__(256) void aeproj_k(const float* __restrict__ ea) {
    __shared__ float w1s[FE * HEADS];
    __shared__ float w2s[FE];
    int tid = threadIdx.x;
    if (tid < FE * HEADS) w1s[tid] = g_wev1[tid];
    if (tid < FE)         w2s[tid] = g_wev2[tid];
    __syncthreads();
    int e = blockIdx.x * 8 + (tid >> 5);
    int lane = tid & 31;
    if (e >= EE) return;
    float v = ea[(size_t)e * FE + lane];
    float p0 = v * w1s[lane * 4 + 0];
    float p1 = v * w1s[lane * 4 + 1];
    float p2 = v * w1s[lane * 4 + 2];
    float p3 = v * w1s[lane * 4 + 3];
    float p4 = v * w2s[lane];
    #pragma unroll
    for (int off = 16; off > 0; off >>= 1) {
        p0 += __shfl_down_sync(0xffffffffu, p0, off);
        p1 += __shfl_down_sync(0xffffffffu, p1, off);
        p2 += __shfl_down_sync(0xffffffffu, p2, off);
        p3 += __shfl_down_sync(0xffffffffu, p3, off);
        p4 += __shfl_down_sync(0xffffffffu, p4, off);
    }
    if (lane == 0) {
        g_aep1[e] = make_float4(p0, p1, p2, p3);
        g_aep2[e] = p4;
    }
}

// ---------------- CSR build (by destination) ----------------
__global__ void hist_k(const int* __restrict__ ei) {
    int j = blockIdx.x * blockDim.x + threadIdx.x;
    if (j >= E2) return;
    int dst = (j < EE) ? ei[EE + j] : ei[j - EE];
    atomicAdd(&g_deg[dst], 1);
}

__global__ __launch_bounds__(1024) void scan_k() {
    __shared__ int part[1024];
    int tid = threadIdx.x;
    const int CH = (NN + 1023) / 1024;
    int base = tid * CH;
    int s = 0;
    for (int i = 0; i < CH; i++) {
        int idx = base + i;
        if (idx < NN) s += g_deg[idx];
    }
    part[tid] = s;
    __syncthreads();
    for (int off = 1; off < 1024; off <<= 1) {
        int v = (tid >= off) ? part[tid - off] : 0;
        __syncthreads();
        part[tid] += v;
        __syncthreads();
    }
    int pre = part[tid] - s; // exclusive prefix
    for (int i = 0; i < CH; i++) {
        int idx = base + i;
        if (idx < NN) {
            g_rowptr[idx] = pre;
            g_cursor[idx] = pre;
            pre += g_deg[idx];
        }
    }
    if (tid == 1023) g_rowptr[NN] = part[1023];
}

__global__ void fill_k(const int* __restrict__ ei) {
    int j = blockIdx.x * blockDim.x + threadIdx.x;
    if (j >= E2) return;
    int srcv, dstv, eid;
    if (j < EE) { srcv = ei[j];       dstv = ei[EE + j]; eid = j; }
    else        { int e = j - EE; srcv = ei[EE + e]; dstv = ei[e]; eid = e; }
    int pos = atomicAdd(&g_cursor[dstv], 1);
    g_csrc[pos] = srcv;
    g_ceid[pos] = eid;
}

// ---------------- SGEMM 128x128x16, 256 thr, 8x8 microtile, f32x2 FMA, dbl-buffer --------
// epi: 0 = none, 2 = bias + PReLU(pa[0]), 3 = bias only
// If sOut != nullptr, fused per-row dot products with aS/aD (column tile == head).
__device__ __forceinline__ ull pack2(float a, float b) {
    ull r;
    asm("mov.b64 %0, {%1, %2};" : "=l"(r) : "f"(a), "f"(b));
    return r;
}
__device__ __forceinline__ void unpack2(ull v, float& lo, float& hi) {
    asm("mov.b64 {%0, %1}, %2;" : "=f"(lo), "=f"(hi) : "l"(v));
}
__device__ __forceinline__ void fma2(ull& acc, ull a, ull b) {
    asm("fma.rn.f32x2 %0, %1, %2, %0;" : "+l"(acc) : "l"(a), "l"(b));
}

__global__ __launch_bounds__(256) void sgemm_k(int M, int N, int K,
        const float* __restrict__ A, const float* __restrict__ B, float* __restrict__ C,
        const float* __restrict__ bias, const float* __restrict__ pa, int epi,
        const float* __restrict__ aS, const float* __restrict__ aD,
        float* __restrict__ sOut, float* __restrict__ dOut, int hs) {
    __shared__ float As[2][16][128];
    __shared__ float Bs[2][16][128];
    int tid = threadIdx.x;
    int rowBase = blockIdx.y * 128;
    int colBase = blockIdx.x * 128;
    int aRow = tid >> 1;
    int aCol = (tid & 1) * 8;
    int bRow = tid >> 4;            // 0..15
    int bCol = (tid & 15) * 8;
    int ty = tid >> 4, tx = tid & 15;
    ull acc[8][4];
    #pragma unroll
    for (int i = 0; i < 8; i++)
        #pragma unroll
        for (int j = 0; j < 4; j++) acc[i][j] = 0ull;

    // prologue: load chunk 0 into buf 0
    {
        int gr = rowBase + aRow;
        float4 a0 = make_float4(0.f, 0.f, 0.f, 0.f), a1 = a0;
        if (gr < M) {
            a0 = *reinterpret_cast<const float4*>(&A[(size_t)gr * K + aCol]);
            a1 = *reinterpret_cast<const float4*>(&A[(size_t)gr * K + aCol + 4]);
        }
        As[0][aCol + 0][aRow] = a0.x; As[0][aCol + 1][aRow] = a0.y;
        As[0][aCol + 2][aRow] = a0.z; As[0][aCol + 3][aRow] = a0.w;
        As[0][aCol + 4][aRow] = a1.x; As[0][aCol + 5][aRow] = a1.y;
        As[0][aCol + 6][aRow] = a1.z; As[0][aCol + 7][aRow] = a1.w;
        *reinterpret_cast<float4*>(&Bs[0][bRow][bCol]) =
            *reinterpret_cast<const float4*>(&B[(size_t)bRow * N + colBase + bCol]);
        *reinterpret_cast<float4*>(&Bs[0][bRow][bCol + 4]) =
            *reinterpret_cast<const float4*>(&B[(size_t)bRow * N + colBase + bCol + 4]);
    }
    __syncthreads();

    int nChunks = K >> 4;
    for (int ch = 0; ch < nChunks; ch++) {
        int buf = ch & 1;
        // prefetch next chunk into buf^1
        if (ch + 1 < nChunks) {
            int k0 = (ch + 1) << 4;
            int gr = rowBase + aRow;
            float4 a0 = make_float4(0.f, 0.f, 0.f, 0.f), a1 = a0;
            if (gr < M) {
                a0 = *reinterpret_cast<const float4*>(&A[(size_t)gr * K + k0 + aCol]);
                a1 = *reinterpret_cast<const float4*>(&A[(size_t)gr * K + k0 + aCol + 4]);
            }
            As[buf ^ 1][aCol + 0][aRow] = a0.x; As[buf ^ 1][aCol + 1][aRow] = a0.y;
            As[buf ^ 1][aCol + 2][aRow] = a0.z; As[buf ^ 1][aCol + 3][aRow] = a0.w;
            As[buf ^ 1][aCol + 4][aRow] = a1.x; As[buf ^ 1][aCol + 5][aRow] = a1.y;
            As[buf ^ 1][aCol + 6][aRow] = a1.z; As[buf ^ 1][aCol + 7][aRow] = a1.w;
            *reinterpret_cast<float4*>(&Bs[buf ^ 1][bRow][bCol]) =
                *reinterpret_cast<const float4*>(&B[(size_t)(k0 + bRow) * N + colBase + bCol]);
            *reinterpret_cast<float4*>(&Bs[buf ^ 1][bRow][bCol + 4]) =
                *reinterpret_cast<const float4*>(&B[(size_t)(k0 + bRow) * N + colBase + bCol + 4]);
        }
        // compute 16 kk-steps from buf
        #pragma unroll
        for (int kk = 0; kk < 16; kk++) {
            const float4* arp = reinterpret_cast<const float4*>(&As[buf][kk][ty * 8]);
            float4 a0 = arp[0], a1 = arp[1];
            ull ap[8];
            ap[0] = pack2(a0.x, a0.x); ap[1] = pack2(a0.y, a0.y);
            ap[2] = pack2(a0.z, a0.z); ap[3] = pack2(a0.w, a0.w);
            ap[4] = pack2(a1.x, a1.x); ap[5] = pack2(a1.y, a1.y);
            ap[6] = pack2(a1.z, a1.z); ap[7] = pack2(a1.w, a1.w);
            ull bp[4];
            const ull* brp = reinterpret_cast<const ull*>(&Bs[buf][kk][tx * 8]);
            bp[0] = brp[0]; bp[1] = brp[1]; bp[2] = brp[2]; bp[3] = brp[3];
            #pragma unroll
            for (int i = 0; i < 8; i++) {
                fma2(acc[i][0], ap[i], bp[0]);
                fma2(acc[i][1], ap[i], bp[1]);
                fma2(acc[i][2], ap[i], bp[2]);
                fma2(acc[i][3], ap[i], bp[3]);
            }
        }
        __syncthreads();
    }

    // unpack accumulators
    float accf[8][8];
    #pragma unroll
    for (int i = 0; i < 8; i++)
        #pragma unroll
        for (int j = 0; j < 4; j++)
            unpack2(acc[i][j], accf[i][2 * j], accf[i][2 * j + 1]);

    float pav = (epi == 2) ? pa[0] : 0.f;
    #pragma unroll
    for (int i = 0; i < 8; i++) {
        int r = rowBase + ty * 8 + i;
        if (r >= M) continue;
        #pragma unroll
        for (int j = 0; j < 8; j++) {
            int c = colBase + tx * 8 + j;
            float v = accf[i][j];
            if (epi) {
                v += bias[c];
                if (epi == 2) v = v > 0.f ? v : pav * v;
            }
            C[(size_t)r * N + c] = v;
        }
    }
    // fused attention dot products: s[r] = C_row . aS[head], d[r] = C_row . aD[head]
    if (sOut) {
        int head = colBase >> 7;
        float avr[8], dvr[8];
        #pragma unroll
        for (int j = 0; j < 8; j++) {
            avr[j] = aS[colBase + tx * 8 + j];
            dvr[j] = aD[colBase + tx * 8 + j];
        }
        #pragma unroll
        for (int i = 0; i < 8; i++) {
            float ps = 0.f, pd = 0.f;
            #pragma unroll
            for (int j = 0; j < 8; j++) { ps += accf[i][j] * avr[j]; pd += accf[i][j] * dvr[j]; }
            #pragma unroll
            for (int off = 8; off > 0; off >>= 1) {
                ps += __shfl_down_sync(0xffffffffu, ps, off, 16);
                pd += __shfl_down_sync(0xffffffffu, pd, off, 16);
            }
            if (tx == 0) {
                int r = rowBase + ty * 8 + i;
                if (r < M) { sOut[(size_t)r * hs + head] = ps; dOut[(size_t)r * hs + head] = pd; }
            }
        }
    }
}

// ---------------- layer-1 softmax weights: warp per node, 4 heads ----------------
__global__ __launch_bounds__(256) void wcalc1_k() {
    int n = blockIdx.x * 8 + (threadIdx.x >> 5);
    if (n >= NN) return;
    int lane = threadIdx.x & 31;
    int start = g_rowptr[n], end = g_rowptr[n + 1];
    if (start == end) return;
    float dl0 = g_d1[n * 4 + 0], dl1 = g_d1[n * 4 + 1];
    float dl2 = g_d1[n * 4 + 2], dl3 = g_d1[n * 4 + 3];
    float m0 = -INFINITY, m1 = -INFINITY, m2 = -INFINITY, m3 = -INFINITY;
    float s0 = 0.f, s1v = 0.f, s2v = 0.f, s3 = 0.f;
    for (int i = start + lane; i < end; i += 32) {
        int sr = g_csrc[i], e = g_ceid[i];
        float4 ap = g_aep1[e];
        float l0 = g_s1[sr * 4 + 0] + dl0 + ap.x; l0 = l0 > 0.f ? l0 : 0.2f * l0;
        float l1 = g_s1[sr * 4 + 1] + dl1 + ap.y; l1 = l1 > 0.f ? l1 : 0.2f * l1;
        float l2 = g_s1[sr * 4 + 2] + dl2 + ap.z; l2 = l2 > 0.f ? l2 : 0.2f * l2;
        float l3 = g_s1[sr * 4 + 3] + dl3 + ap.w; l3 = l3 > 0.f ? l3 : 0.2f * l3;
        g_w1[i] = make_float4(l0, l1, l2, l3);
        float nm;
        nm = fmaxf(m0, l0); s0  = s0  * __expf(m0 - nm) + __expf(l0 - nm); m0 = nm;
        nm = fmaxf(m1, l1); s1v = s1v * __expf(m1 - nm) + __expf(l1 - nm); m1 = nm;
        nm = fmaxf(m2, l2); s2v = s2v * __expf(m2 - nm) + __expf(l2 - nm); m2 = nm;
        nm = fmaxf(m3, l3); s3  = s3  * __expf(m3 - nm) + __expf(l3 - nm); m3 = nm;
    }
    #pragma unroll
    for (int off = 16; off > 0; off >>= 1) {
        float om, os, nm, a, b;
        om = __shfl_xor_sync(0xffffffffu, m0, off); os = __shfl_xor_sync(0xffffffffu, s0, off);
        nm = fmaxf(m0, om);
        a = (m0 == nm) ? s0 : s0 * __expf(m0 - nm);
        b = (om == nm) ? os : os * __expf(om - nm);
        s0 = a + b; m0 = nm;
        om = __shfl_xor_sync(0xffffffffu, m1, off); os = __shfl_xor_sync(0xffffffffu, s1v, off);
        nm = fmaxf(m1, om);
        a = (m1 == nm) ? s1v : s1v * __expf(m1 - nm);
        b = (om == nm) ? os : os * __expf(om - nm);
        s1v = a + b; m1 = nm;
        om = __shfl_xor_sync(0xffffffffu, m2, off); os = __shfl_xor_sync(0xffffffffu, s2v, off);
        nm = fmaxf(m2, om);
        a = (m2 == nm) ? s2v : s2v * __expf(m2 - nm);
        b = (om == nm) ? os : os * __expf(om - nm);
        s2v = a + b; m2 = nm;
        om = __shfl_xor_sync(0xffffffffu, m3, off); os = __shfl_xor_sync(0xffffffffu, s3, off);
        nm = fmaxf(m3, om);
        a = (m3 == nm) ? s3 : s3 * __expf(m3 - nm);
        b = (om == nm) ? os : os * __expf(om - nm);
        s3 = a + b; m3 = nm;
    }
    float i0 = 1.f / s0, i1 = 1.f / s1v, i2 = 1.f / s2v, i3 = 1.f / s3;
    for (int i = start + lane; i < end; i += 32) {
        float4 l = g_w1[i];
        g_w1[i] = make_float4(__expf(l.x - m0) * i0, __expf(l.y - m1) * i1,
                              __expf(l.z - m2) * i2, __expf(l.w - m3) * i3);
    }
}

// ---------------- layer-2 softmax weights: warp per node, 1 head ----------------
__global__ __launch_bounds__(256) void wcalc2_k() {
    int n = blockIdx.x * 8 + (threadIdx.x >> 5);
    if (n >= NN) return;
    int lane = threadIdx.x & 31;
    int start = g_rowptr[n], end = g_rowptr[n + 1];
    if (start == end) return;
    float dl = g_d2[n];
    float m = -INFINITY, s = 0.f;
    for (int i = start + lane; i < end; i += 32) {
        int sr = g_csrc[i], e = g_ceid[i];
        float l = g_s2[sr] + dl + g_aep2[e];
        l = l > 0.f ? l : 0.2f * l;
        g_w2[i] = l;
        float nm = fmaxf(m, l);
        s = s * __expf(m - nm) + __expf(l - nm);
        m = nm;
    }
    #pragma unroll
    for (int off = 16; off > 0; off >>= 1) {
        float om = __shfl_xor_sync(0xffffffffu, m, off);
        float os = __shfl_xor_sync(0xffffffffu, s, off);
        float nm = fmaxf(m, om);
        float a = (m == nm) ? s : s * __expf(m - nm);
        float b = (om == nm) ? os : os * __expf(om - nm);
        s = a + b; m = nm;
    }
    float inv = 1.f / s;
    for (int i = start + lane; i < end; i += 32)
        g_w2[i] = __expf(g_w2[i] - m) * inv;
}

// ---------------- layer-1 aggregation: pure weighted gather, 512 ch ----------------
__global__ __launch_bounds__(128) void agg1_k(const float* __restrict__ h1,
        const float* __restrict__ bias, float* __restrict__ out) {
    int n = blockIdx.x, tid = threadIdx.x;
    int start = g_rowptr[n], end = g_rowptr[n + 1];
    __shared__ int src_sh[128];
    __shared__ float4 w_sh[128];
    int hsel = tid >> 5;  // head index (warp-uniform)
    float4 acc = make_float4(0.f, 0.f, 0.f, 0.f);
    for (int t0 = start; t0 < end; t0 += 128) {
        int cnt = min(128, end - t0);
        if (tid < cnt) { src_sh[tid] = g_csrc[t0 + tid]; w_sh[tid] = g_w1[t0 + tid]; }
        __syncthreads();
        #pragma unroll 4
        for (int e = 0; e < cnt; e++) {
            int s = src_sh[e];
            float wv = reinterpret_cast<const float*>(&w_sh[e])[hsel];
            float4 hv = *reinterpret_cast<const float4*>(&h1[(size_t)s * D1 + tid * 4]);
            acc.x += hv.x * wv; acc.y += hv.y * wv; acc.z += hv.z * wv; acc.w += hv.w * wv;
        }
        __syncthreads();
    }
    const float4 bv = *reinterpret_cast<const float4*>(&bias[tid * 4]);
    float o0 = acc.x + bv.x, o1 = acc.y + bv.y, o2 = acc.z + bv.z, o3 = acc.w + bv.w;
    o0 = o0 > 0.f ? o0 : (__expf(o0) - 1.f);
    o1 = o1 > 0.f ? o1 : (__expf(o1) - 1.f);
    o2 = o2 > 0.f ? o2 : (__expf(o2) - 1.f);
    o3 = o3 > 0.f ? o3 : (__expf(o3) - 1.f);
    *reinterpret_cast<float4*>(&out[(size_t)n * D1 + tid * 4]) = make_float4(o0, o1, o2, o3);
}

// ---------------- layer-2 aggregation: warp per node, 128 ch ----------------
__global__ __launch_bounds__(256) void agg2_k(const float* __restrict__ h2t,
        const float* __restrict__ bias, float* __restrict__ out) {
    int n = blockIdx.x * 8 + (threadIdx.x >> 5);
    if (n >= NN) return;
    int lane = threadIdx.x & 31;
    int start = g_rowptr[n], end = g_rowptr[n + 1];
    float4 acc = make_float4(0.f, 0.f, 0.f, 0.f);
    for (int t0 = start; t0 < end; t0 += 32) {
        int cnt = min(32, end - t0);
        int sr = 0; float wv = 0.f;
        if (lane < cnt) { sr = g_csrc[t0 + lane]; wv = g_w2[t0 + lane]; }
        for (int j = 0; j < cnt; j++) {
            int s = __shfl_sync(0xffffffffu, sr, j);
            float w = __shfl_sync(0xffffffffu, wv, j);
            float4 hv = *reinterpret_cast<const float4*>(&h2t[(size_t)s * HID + lane * 4]);
            acc.x += hv.x * w; acc.y += hv.y * w; acc.z += hv.z * w; acc.w += hv.w * w;
        }
    }
    const float4 bv = *reinterpret_cast<const float4*>(&bias[lane * 4]);
    float o0 = acc.x + bv.x, o1 = acc.y + bv.y, o2 = acc.z + bv.z, o3 = acc.w + bv.w;
    o0 = o0 > 0.f ? o0 : (__expf(o0) - 1.f);
    o1 = o1 > 0.f ? o1 : (__expf(o1) - 1.f);
    o2 = o2 > 0.f ? o2 : (__expf(o2) - 1.f);
    o3 = o3 > 0.f ? o3 : (__expf(o3) - 1.f);
    *reinterpret_cast<float4*>(&out[(size_t)n * HID + lane * 4]) = make_float4(o0, o1, o2, o3);
}

// ---------------- column mean + sigmoid ----------------
__global__ void colsum_k(const float* __restrict__ hp) {
    int col = threadIdx.x;
    float acc = 0.f;
    for (int r = blockIdx.x; r < NN; r += gridDim.x) acc += hp[(size_t)r * HID + col];
    atomicAdd(&g_colsum[col], acc);
}

__global__ void final_k(float* __restrict__ outg) {
    int t = threadIdx.x;
    if (t < HID) {
        float m = g_colsum[t] / (float)NN;
        outg[t] = 1.f / (1.f + __expf(-m));
    }
}

// ---------------- launch ----------------
extern "C" void kernel_launch(void* const* d_in, const int* in_sizes, int n_in,
                              void* d_out, int out_size) {
    const float* x   = (const float*)d_in[0];
    const int*   ei  = (const int*)  d_in[1];
    const float* ea  = (const float*)d_in[2];
    const float* W1  = (const float*)d_in[3];
    const float* We1 = (const float*)d_in[4];
    const float* as1 = (const float*)d_in[5];
    const float* ad1 = (const float*)d_in[6];
    const float* ae1 = (const float*)d_in[7];
    const float* b1  = (const float*)d_in[8];
    const float* W2  = (const float*)d_in[9];
    const float* We2 = (const float*)d_in[10];
    const float* as2 = (const float*)d_in[11];
    const float* ad2 = (const float*)d_in[12];
    const float* ae2 = (const float*)d_in[13];
    const float* b2  = (const float*)d_in[14];
    const float* P1  = (const float*)d_in[15];
    const float* pb1 = (const float*)d_in[16];
    const float* pa  = (const float*)d_in[17];
    const float* P2  = (const float*)d_in[18];
    const float* pb2 = (const float*)d_in[19];
    float* out = (float*)d_out;

    float *p_h1, *p_out1, *p_h2t, *p_h2, *p_z, *p_s1, *p_d1, *p_s2, *p_d2;
    cudaGetSymbolAddress((void**)&p_h1,   g_h1);
    cudaGetSymbolAddress((void**)&p_out1, g_out1);
    cudaGetSymbolAddress((void**)&p_h2t,  g_h2t);
    cudaGetSymbolAddress((void**)&p_h2,   g_h2);
    cudaGetSymbolAddress((void**)&p_z,    g_z);
    cudaGetSymbolAddress((void**)&p_s1,   g_s1);
    cudaGetSymbolAddress((void**)&p_d1,   g_d1);
    cudaGetSymbolAddress((void**)&p_s2,   g_s2);
    cudaGetSymbolAddress((void**)&p_d2,   g_d2);

    zero_k<<<(NN + 255) / 256, 256>>>();
    wev_k<<<1, FE * HEADS + FE>>>(We1, ae1, We2, ae2);
    aeproj_k<<<(EE + 7) / 8, 256>>>(ea);
    hist_k<<<(E2 + 255) / 256, 256>>>(ei);
    scan_k<<<1, 1024>>>();
    fill_k<<<(E2 + 255) / 256, 256>>>(ei);

    // layer 1: GEMM with fused attention dots
    sgemm_k<<<dim3(D1 / 128, (NN + 127) / 128), 256>>>(NN, D1, FIN, x, W1, p_h1,
            nullptr, nullptr, 0, as1, ad1, p_s1, p_d1, HEADS);
    wcalc1_k<<<(NN + 7) / 8, 256>>>();
    agg1_k<<<NN, 128>>>(p_h1, b1, p_out1);

    // layer 2
    sgemm_k<<<dim3(1, (NN + 127) / 128), 256>>>(NN, HID, D1, p_out1, W2, p_h2t,
            nullptr, nullptr, 0, as2, ad2, p_s2, p_d2, 1);
    wcalc2_k<<<(NN + 7) / 8, 256>>>();
    agg2_k<<<(NN + 7) / 8, 256>>>(p_h2t, b2, p_h2);

    // projection head
    sgemm_k<<<dim3(1, (NN + 127) / 128), 256>>>(NN, HID, HID, p_h2, P1, p_z,
            pb1, pa, 2, nullptr, nullptr, nullptr, nullptr, 1);
    sgemm_k<<<dim3(1, (NN + 127) / 128), 256>>>(NN, HID, HID, p_z, P2, out,
            pb2, nullptr, 3, nullptr, nullptr, nullptr, nullptr, 1);

    // g = sigmoid(mean(h_proj, axis=0))
    colsum_k<<<128, 128>>>(out);
    final_k<<<1, 128>>>(out + (size_t)NN * HID);
}

// round 7
// speedup vs baseline: 1.2127x; 1.0009x over previous
#include <cuda_runtime.h>
#include <cuda_bf16.h>
#include <math.h>
#include <stdint.h>

// ---------------- problem constants ----------------
constexpr int NN   = 20000;    // nodes
constexpr int EE   = 320000;   // edges (before doubling)
constexpr int E2   = 2 * EE;   // doubled edges
constexpr int FIN  = 256;
constexpr int FE   = 32;
constexpr int HID  = 128;
constexpr int HEADS = 4;
constexpr int D1   = HEADS * HID; // 512

typedef unsigned long long ull;

// ---------------- device scratch (static, no allocs) ----------------
__device__ __align__(16) float g_h1   [(size_t)NN * D1];   // x@W1
__device__ __align__(16) float g_out1 [(size_t)NN * D1];   // layer1 output (post ELU)
__device__ __align__(16) float g_h2t  [(size_t)NN * HID];  // h@W2
__device__ __align__(16) float g_h2   [(size_t)NN * HID];  // layer2 output (post ELU)
__device__ __align__(16) float g_z    [(size_t)NN * HID];  // proj1 output (post PReLU)
__device__ __align__(16) float g_s1   [NN * HEADS];
__device__ __align__(16) float g_d1   [NN * HEADS];
__device__ float g_s2   [NN];
__device__ float g_d2   [NN];
__device__ float4 g_aep1 [EE];     // per-edge logit contribution, 4 heads
__device__ float  g_aep2 [EE];
__device__ float4 g_w1   [E2];     // per-CSR-slot: logits then normalized weights (4 heads)
__device__ float  g_w2   [E2];     // layer-2 weights per CSR slot
__device__ float g_wev1 [FE * HEADS];
__device__ float g_wev2 [FE];
__device__ int   g_deg  [NN];
__device__ int   g_rowptr[NN + 1];
__device__ int   g_cursor[NN];
__device__ int   g_csrc [E2];
__device__ int   g_ceid [E2];
__device__ float g_colsum[HID];

// ---------------- small helpers ----------------
__global__ void zero_k() {
    int i = blockIdx.x * blockDim.x + threadIdx.x;
    if (i < NN) g_deg[i] = 0;
    if (i < HID) g_colsum[i] = 0.f;
}

// wev1[f*4+h] = sum_c We1[f,h*128+c]*ae1[h,c];  wev2[f] = sum_c We2[f,c]*ae2[c]
__global__ void wev_k(const float* __restrict__ We1, const float* __restrict__ ae1,
                      const float* __restrict__ We2, const float* __restrict__ ae2) {
    int t = threadIdx.x;
    if (t < FE * HEADS) {
        int f = t >> 2, h = t & 3;
        float s = 0.f;
        for (int c = 0; c < HID; c++) s += We1[(size_t)f * D1 + h * HID + c] * ae1[h * HID + c];
        g_wev1[t] = s;
    } else if (t < FE * HEADS + FE) {
        int f = t - FE * HEADS;
        float s = 0.f;
        for (int c = 0; c < HID; c++) s += We2[(size_t)f * HID + c] * ae2[c];
        g_wev2[f] = s;
    }
}

// per-edge logit contributions: aep1[e][h] = ea[e,:] . wev1[:,h]; aep2[e] = ea[e,:] . wev2
__global__ __launch_bounds__(256) void aeproj_k(const float* __restrict__ ea) {
    __shared__ float w1s[FE * HEADS];
    __shared__ float w2s[FE];
    int tid = threadIdx.x;
    if (tid < FE * HEADS) w1s[tid] = g_wev1[tid];
    if (tid < FE)         w2s[tid] = g_wev2[tid];
    __syncthreads();
    int e = blockIdx.x * 8 + (tid >> 5);
    int lane = tid & 31;
    if (e >= EE) return;
    float v = ea[(size_t)e * FE + lane];
    float p0 = v * w1s[lane * 4 + 0];
    float p1 = v * w1s[lane * 4 + 1];
    float p2 = v * w1s[lane * 4 + 2];
    float p3 = v * w1s[lane * 4 + 3];
    float p4 = v * w2s[lane];
    #pragma unroll
    for (int off = 16; off > 0; off >>= 1) {
        p0 += __shfl_down_sync(0xffffffffu, p0, off);
        p1 += __shfl_down_sync(0xffffffffu, p1, off);
        p2 += __shfl_down_sync(0xffffffffu, p2, off);
        p3 += __shfl_down_sync(0xffffffffu, p3, off);
        p4 += __shfl_down_sync(0xffffffffu, p4, off);
    }
    if (lane == 0) {
        g_aep1[e] = make_float4(p0, p1, p2, p3);
        g_aep2[e] = p4;
    }
}

// ---------------- CSR build (by destination) ----------------
__global__ void hist_k(const int* __restrict__ ei) {
    int j = blockIdx.x * blockDim.x + threadIdx.x;
    if (j >= E2) return;
    int dst = (j < EE) ? ei[EE + j] : ei[j - EE];
    atomicAdd(&g_deg[dst], 1);
}

__global__ __launch_bounds__(1024) void scan_k() {
    __shared__ int part[1024];
    int tid = threadIdx.x;
    const int CH = (NN + 1023) / 1024;
    int base = tid * CH;
    int s = 0;
    for (int i = 0; i < CH; i++) {
        int idx = base + i;
        if (idx < NN) s += g_deg[idx];
    }
    part[tid] = s;
    __syncthreads();
    for (int off = 1; off < 1024; off <<= 1) {
        int v = (tid >= off) ? part[tid - off] : 0;
        __syncthreads();
        part[tid] += v;
        __syncthreads();
    }
    int pre = part[tid] - s; // exclusive prefix
    for (int i = 0; i < CH; i++) {
        int idx = base + i;
        if (idx < NN) {
            g_rowptr[idx] = pre;
            g_cursor[idx] = pre;
            pre += g_deg[idx];
        }
    }
    if (tid == 1023) g_rowptr[NN] = part[1023];
}

__global__ void fill_k(const int* __restrict__ ei) {
    int j = blockIdx.x * blockDim.x + threadIdx.x;
    if (j >= E2) return;
    int srcv, dstv, eid;
    if (j < EE) { srcv = ei[j];       dstv = ei[EE + j]; eid = j; }
    else        { int e = j - EE; srcv = ei[EE + e]; dstv = ei[e]; eid = e; }
    int pos = atomicAdd(&g_cursor[dstv], 1);
    g_csrc[pos] = srcv;
    g_ceid[pos] = eid;
}

// ---------------- SGEMM 128x128x16, 256 thr, 8x8 microtile, f32x2 FMA, dbl-buffer --------
// epi: 0 = none, 2 = bias + PReLU(pa[0]), 3 = bias only
// If sOut != nullptr, fused per-row dot products with aS/aD (column tile == head).
__device__ __forceinline__ ull pack2(float a, float b) {
    ull r;
    asm("mov.b64 %0, {%1, %2};" : "=l"(r) : "f"(a), "f"(b));
    return r;
}
__device__ __forceinline__ void unpack2(ull v, float& lo, float& hi) {
    asm("mov.b64 {%0, %1}, %2;" : "=f"(lo), "=f"(hi) : "l"(v));
}
__device__ __forceinline__ void fma2(ull& acc, ull a, ull b) {
    asm("fma.rn.f32x2 %0, %1, %2, %0;" : "+l"(acc) : "l"(a), "l"(b));
}

__global__ __launch_bounds__(256) void sgemm_k(int M, int N, int K,
        const float* __restrict__ A, const float* __restrict__ B, float* __restrict__ C,
        const float* __restrict__ bias, const float* __restrict__ pa, int epi,
        const float* __restrict__ aS, const float* __restrict__ aD,
        float* __restrict__ sOut, float* __restrict__ dOut, int hs) {
    __shared__ float As[2][16][128];
    __shared__ float Bs[2][16][128];
    int tid = threadIdx.x;
    int rowBase = blockIdx.y * 128;
    int colBase = blockIdx.x * 128;
    int aRow = tid >> 1;
    int aCol = (tid & 1) * 8;
    int bRow = tid >> 4;            // 0..15
    int bCol = (tid & 15) * 8;
    int ty = tid >> 4, tx = tid & 15;
    ull acc[8][4];
    #pragma unroll
    for (int i = 0; i < 8; i++)
        #pragma unroll
        for (int j = 0; j < 4; j++) acc[i][j] = 0ull;

    // prologue: load chunk 0 into buf 0
    {
        int gr = rowBase + aRow;
        float4 a0 = make_float4(0.f, 0.f, 0.f, 0.f), a1 = a0;
        if (gr < M) {
            a0 = *reinterpret_cast<const float4*>(&A[(size_t)gr * K + aCol]);
            a1 = *reinterpret_cast<const float4*>(&A[(size_t)gr * K + aCol + 4]);
        }
        As[0][aCol + 0][aRow] = a0.x; As[0][aCol + 1][aRow] = a0.y;
        As[0][aCol + 2][aRow] = a0.z; As[0][aCol + 3][aRow] = a0.w;
        As[0][aCol + 4][aRow] = a1.x; As[0][aCol + 5][aRow] = a1.y;
        As[0][aCol + 6][aRow] = a1.z; As[0][aCol + 7][aRow] = a1.w;
        *reinterpret_cast<float4*>(&Bs[0][bRow][bCol]) =
            *reinterpret_cast<const float4*>(&B[(size_t)bRow * N + colBase + bCol]);
        *reinterpret_cast<float4*>(&Bs[0][bRow][bCol + 4]) =
            *reinterpret_cast<const float4*>(&B[(size_t)bRow * N + colBase + bCol + 4]);
    }
    __syncthreads();

    int nChunks = K >> 4;
    for (int ch = 0; ch < nChunks; ch++) {
        int buf = ch & 1;
        // prefetch next chunk into buf^1
        if (ch + 1 < nChunks) {
            int k0 = (ch + 1) << 4;
            int gr = rowBase + aRow;
            float4 a0 = make_float4(0.f, 0.f, 0.f, 0.f), a1 = a0;
            if (gr < M) {
                a0 = *reinterpret_cast<const float4*>(&A[(size_t)gr * K + k0 + aCol]);
                a1 = *reinterpret_cast<const float4*>(&A[(size_t)gr * K + k0 + aCol + 4]);
            }
            As[buf ^ 1][aCol + 0][aRow] = a0.x; As[buf ^ 1][aCol + 1][aRow] = a0.y;
            As[buf ^ 1][aCol + 2][aRow] = a0.z; As[buf ^ 1][aCol + 3][aRow] = a0.w;
            As[buf ^ 1][aCol + 4][aRow] = a1.x; As[buf ^ 1][aCol + 5][aRow] = a1.y;
            As[buf ^ 1][aCol + 6][aRow] = a1.z; As[buf ^ 1][aCol + 7][aRow] = a1.w;
            *reinterpret_cast<float4*>(&Bs[buf ^ 1][bRow][bCol]) =
                *reinterpret_cast<const float4*>(&B[(size_t)(k0 + bRow) * N + colBase + bCol]);
            *reinterpret_cast<float4*>(&Bs[buf ^ 1][bRow][bCol + 4]) =
                *reinterpret_cast<const float4*>(&B[(size_t)(k0 + bRow) * N + colBase + bCol + 4]);
        }
        // compute 16 kk-steps from buf
        #pragma unroll
        for (int kk = 0; kk < 16; kk++) {
            const float4* arp = reinterpret_cast<const float4*>(&As[buf][kk][ty * 8]);
            float4 a0 = arp[0], a1 = arp[1];
            ull ap[8];
            ap[0] = pack2(a0.x, a0.x); ap[1] = pack2(a0.y, a0.y);
            ap[2] = pack2(a0.z, a0.z); ap[3] = pack2(a0.w, a0.w);
            ap[4] = pack2(a1.x, a1.x); ap[5] = pack2(a1.y, a1.y);
            ap[6] = pack2(a1.z, a1.z); ap[7] = pack2(a1.w, a1.w);
            ull bp[4];
            const ull* brp = reinterpret_cast<const ull*>(&Bs[buf][kk][tx * 8]);
            bp[0] = brp[0]; bp[1] = brp[1]; bp[2] = brp[2]; bp[3] = brp[3];
            #pragma unroll
            for (int i = 0; i < 8; i++) {
                fma2(acc[i][0], ap[i], bp[0]);
                fma2(acc[i][1], ap[i], bp[1]);
                fma2(acc[i][2], ap[i], bp[2]);
                fma2(acc[i][3], ap[i], bp[3]);
            }
        }
        __syncthreads();
    }

    // unpack accumulators
    float accf[8][8];
    #pragma unroll
    for (int i = 0; i < 8; i++)
        #pragma unroll
        for (int j = 0; j < 4; j++)
            unpack2(acc[i][j], accf[i][2 * j], accf[i][2 * j + 1]);

    float pav = (epi == 2) ? pa[0] : 0.f;
    #pragma unroll
    for (int i = 0; i < 8; i++) {
        int r = rowBase + ty * 8 + i;
        if (r >= M) continue;
        #pragma unroll
        for (int j = 0; j < 8; j++) {
            int c = colBase + tx * 8 + j;
            float v = accf[i][j];
            if (epi) {
                v += bias[c];
                if (epi == 2) v = v > 0.f ? v : pav * v;
            }
            C[(size_t)r * N + c] = v;
        }
    }
    // fused attention dot products: s[r] = C_row . aS[head], d[r] = C_row . aD[head]
    if (sOut) {
        int head = colBase >> 7;
        float avr[8], dvr[8];
        #pragma unroll
        for (int j = 0; j < 8; j++) {
            avr[j] = aS[colBase + tx * 8 + j];
            dvr[j] = aD[colBase + tx * 8 + j];
        }
        #pragma unroll
        for (int i = 0; i < 8; i++) {
            float ps = 0.f, pd = 0.f;
            #pragma unroll
            for (int j = 0; j < 8; j++) { ps += accf[i][j] * avr[j]; pd += accf[i][j] * dvr[j]; }
            #pragma unroll
            for (int off = 8; off > 0; off >>= 1) {
                ps += __shfl_down_sync(0xffffffffu, ps, off, 16);
                pd += __shfl_down_sync(0xffffffffu, pd, off, 16);
            }
            if (tx == 0) {
                int r = rowBase + ty * 8 + i;
                if (r < M) { sOut[(size_t)r * hs + head] = ps; dOut[(size_t)r * hs + head] = pd; }
            }
        }
    }
}

// ---------------- layer-1 softmax weights: warp per node, 4 heads ----------------
__global__ __launch_bounds__(256) void wcalc1_k() {
    int n = blockIdx.x * 8 + (threadIdx.x >> 5);
    if (n >= NN) return;
    int lane = threadIdx.x & 31;
    int start = g_rowptr[n], end = g_rowptr[n + 1];
    if (start == end) return;
    float dl0 = g_d1[n * 4 + 0], dl1 = g_d1[n * 4 + 1];
    float dl2 = g_d1[n * 4 + 2], dl3 = g_d1[n * 4 + 3];
    float m0 = -INFINITY, m1 = -INFINITY, m2 = -INFINITY, m3 = -INFINITY;
    float s0 = 0.f, s1v = 0.f, s2v = 0.f, s3 = 0.f;
    for (int i = start + lane; i < end; i += 32) {
        int sr = g_csrc[i], e = g_ceid[i];
        float4 ap = g_aep1[e];
        float l0 = g_s1[sr * 4 + 0] + dl0 + ap.x; l0 = l0 > 0.f ? l0 : 0.2f * l0;
        float l1 = g_s1[sr * 4 + 1] + dl1 + ap.y; l1 = l1 > 0.f ? l1 : 0.2f * l1;
        float l2 = g_s1[sr * 4 + 2] + dl2 + ap.z; l2 = l2 > 0.f ? l2 : 0.2f * l2;
        float l3 = g_s1[sr * 4 + 3] + dl3 + ap.w; l3 = l3 > 0.f ? l3 : 0.2f * l3;
        g_w1[i] = make_float4(l0, l1, l2, l3);
        float nm;
        nm = fmaxf(m0, l0); s0  = s0  * __expf(m0 - nm) + __expf(l0 - nm); m0 = nm;
        nm = fmaxf(m1, l1); s1v = s1v * __expf(m1 - nm) + __expf(l1 - nm); m1 = nm;
        nm = fmaxf(m2, l2); s2v = s2v * __expf(m2 - nm) + __expf(l2 - nm); m2 = nm;
        nm = fmaxf(m3, l3); s3  = s3  * __expf(m3 - nm) + __expf(l3 - nm); m3 = nm;
    }
    #pragma unroll
    for (int off = 16; off > 0; off >>= 1) {
        float om, os, nm, a, b;
        om = __shfl_xor_sync(0xffffffffu, m0, off); os = __shfl_xor_sync(0xffffffffu, s0, off);
        nm = fmaxf(m0, om);
        a = (m0 == nm) ? s0 : s0 * __expf(m0 - nm);
        b = (om == nm) ? os : os * __expf(om - nm);
        s0 = a + b; m0 = nm;
        om = __shfl_xor_sync(0xffffffffu, m1, off); os = __shfl_xor_sync(0xffffffffu, s1v, off);
        nm = fmaxf(m1, om);
        a = (m1 == nm) ? s1v : s1v * __expf(m1 - nm);
        b = (om == nm) ? os : os * __expf(om - nm);
        s1v = a + b; m1 = nm;
        om = __shfl_xor_sync(0xffffffffu, m2, off); os = __shfl_xor_sync(0xffffffffu, s2v, off);
        nm = fmaxf(m2, om);
        a = (m2 == nm) ? s2v : s2v * __expf(m2 - nm);
        b = (om == nm) ? os : os * __expf(om - nm);
        s2v = a + b; m2 = nm;
        om = __shfl_xor_sync(0xffffffffu, m3, off); os = __shfl_xor_sync(0xffffffffu, s3, off);
        nm = fmaxf(m3, om);
        a = (m3 == nm) ? s3 : s3 * __expf(m3 - nm);
        b = (om == nm) ? os : os * __expf(om - nm);
        s3 = a + b; m3 = nm;
    }
    float i0 = 1.f / s0, i1 = 1.f / s1v, i2 = 1.f / s2v, i3 = 1.f / s3;
    for (int i = start + lane; i < end; i += 32) {
        float4 l = g_w1[i];
        g_w1[i] = make_float4(__expf(l.x - m0) * i0, __expf(l.y - m1) * i1,
                              __expf(l.z - m2) * i2, __expf(l.w - m3) * i3);
    }
}

// ---------------- layer-2 softmax weights: warp per node, 1 head ----------------
__global__ __launch_bounds__(256) void wcalc2_k() {
    int n = blockIdx.x * 8 + (threadIdx.x >> 5);
    if (n >= NN) return;
    int lane = threadIdx.x & 31;
    int start = g_rowptr[n], end = g_rowptr[n + 1];
    if (start == end) return;
    float dl = g_d2[n];
    float m = -INFINITY, s = 0.f;
    for (int i = start + lane; i < end; i += 32) {
        int sr = g_csrc[i], e = g_ceid[i];
        float l = g_s2[sr] + dl + g_aep2[e];
        l = l > 0.f ? l : 0.2f * l;
        g_w2[i] = l;
        float nm = fmaxf(m, l);
        s = s * __expf(m - nm) + __expf(l - nm);
        m = nm;
    }
    #pragma unroll
    for (int off = 16; off > 0; off >>= 1) {
        float om = __shfl_xor_sync(0xffffffffu, m, off);
        float os = __shfl_xor_sync(0xffffffffu, s, off);
        float nm = fmaxf(m, om);
        float a = (m == nm) ? s : s * __expf(m - nm);
        float b = (om == nm) ? os : os * __expf(om - nm);
        s = a + b; m = nm;
    }
    float inv = 1.f / s;
    for (int i = start + lane; i < end; i += 32)
        g_w2[i] = __expf(g_w2[i] - m) * inv;
}

// ---------------- layer-1 aggregation: pure weighted gather, 512 ch ----------------
__global__ __launch_bounds__(128) void agg1_k(const float* __restrict__ h1,
        const float* __restrict__ bias, float* __restrict__ out) {
    int n = blockIdx.x, tid = threadIdx.x;
    int start = g_rowptr[n], end = g_rowptr[n + 1];
    __shared__ int src_sh[128];
    __shared__ float4 w_sh[128];
    int hsel = tid >> 5;  // head index (warp-uniform)
    float4 acc = make_float4(0.f, 0.f, 0.f, 0.f);
    for (int t0 = start; t0 < end; t0 += 128) {
        int cnt = min(128, end - t0);
        if (tid < cnt) { src_sh[tid] = g_csrc[t0 + tid]; w_sh[tid] = g_w1[t0 + tid]; }
        __syncthreads();
        #pragma unroll 4
        for (int e = 0; e < cnt; e++) {
            int s = src_sh[e];
            float wv = reinterpret_cast<const float*>(&w_sh[e])[hsel];
            float4 hv = *reinterpret_cast<const float4*>(&h1[(size_t)s * D1 + tid * 4]);
            acc.x += hv.x * wv; acc.y += hv.y * wv; acc.z += hv.z * wv; acc.w += hv.w * wv;
        }
        __syncthreads();
    }
    const float4 bv = *reinterpret_cast<const float4*>(&bias[tid * 4]);
    float o0 = acc.x + bv.x, o1 = acc.y + bv.y, o2 = acc.z + bv.z, o3 = acc.w + bv.w;
    o0 = o0 > 0.f ? o0 : (__expf(o0) - 1.f);
    o1 = o1 > 0.f ? o1 : (__expf(o1) - 1.f);
    o2 = o2 > 0.f ? o2 : (__expf(o2) - 1.f);
    o3 = o3 > 0.f ? o3 : (__expf(o3) - 1.f);
    *reinterpret_cast<float4*>(&out[(size_t)n * D1 + tid * 4]) = make_float4(o0, o1, o2, o3);
}

// ---------------- layer-2 aggregation: warp per node, 128 ch ----------------
__global__ __launch_bounds__(256) void agg2_k(const float* __restrict__ h2t,
        const float* __restrict__ bias, float* __restrict__ out) {
    int n = blockIdx.x * 8 + (threadIdx.x >> 5);
    if (n >= NN) return;
    int lane = threadIdx.x & 31;
    int start = g_rowptr[n], end = g_rowptr[n + 1];
    float4 acc = make_float4(0.f, 0.f, 0.f, 0.f);
    for (int t0 = start; t0 < end; t0 += 32) {
        int cnt = min(32, end - t0);
        int sr = 0; float wv = 0.f;
        if (lane < cnt) { sr = g_csrc[t0 + lane]; wv = g_w2[t0 + lane]; }
        for (int j = 0; j < cnt; j++) {
            int s = __shfl_sync(0xffffffffu, sr, j);
            float w = __shfl_sync(0xffffffffu, wv, j);
            float4 hv = *reinterpret_cast<const float4*>(&h2t[(size_t)s * HID + lane * 4]);
            acc.x += hv.x * w; acc.y += hv.y * w; acc.z += hv.z * w; acc.w += hv.w * w;
        }
    }
    const float4 bv = *reinterpret_cast<const float4*>(&bias[lane * 4]);
    float o0 = acc.x + bv.x, o1 = acc.y + bv.y, o2 = acc.z + bv.z, o3 = acc.w + bv.w;
    o0 = o0 > 0.f ? o0 : (__expf(o0) - 1.f);
    o1 = o1 > 0.f ? o1 : (__expf(o1) - 1.f);
    o2 = o2 > 0.f ? o2 : (__expf(o2) - 1.f);
    o3 = o3 > 0.f ? o3 : (__expf(o3) - 1.f);
    *reinterpret_cast<float4*>(&out[(size_t)n * HID + lane * 4]) = make_float4(o0, o1, o2, o3);
}

// ---------------- column mean + sigmoid ----------------
__global__ void colsum_k(const float* __restrict__ hp) {
    int col = threadIdx.x;
    float acc = 0.f;
    for (int r = blockIdx.x; r < NN; r += gridDim.x) acc += hp[(size_t)r * HID + col];
    atomicAdd(&g_colsum[col], acc);
}

__global__ void final_k(float* __restrict__ outg) {
    int t = threadIdx.x;
    if (t < HID) {
        float m = g_colsum[t] / (float)NN;
        outg[t] = 1.f / (1.f + __expf(-m));
    }
}

// ---------------- launch ----------------
extern "C" void kernel_launch(void* const* d_in, const int* in_sizes, int n_in,
                              void* d_out, int out_size) {
    const float* x   = (const float*)d_in[0];
    const int*   ei  = (const int*)  d_in[1];
    const float* ea  = (const float*)d_in[2];
    const float* W1  = (const float*)d_in[3];
    const float* We1 = (const float*)d_in[4];
    const float* as1 = (const float*)d_in[5];
    const float* ad1 = (const float*)d_in[6];
    const float* ae1 = (const float*)d_in[7];
    const float* b1  = (const float*)d_in[8];
    const float* W2  = (const float*)d_in[9];
    const float* We2 = (const float*)d_in[10];
    const float* as2 = (const float*)d_in[11];
    const float* ad2 = (const float*)d_in[12];
    const float* ae2 = (const float*)d_in[13];
    const float* b2  = (const float*)d_in[14];
    const float* P1  = (const float*)d_in[15];
    const float* pb1 = (const float*)d_in[16];
    const float* pa  = (const float*)d_in[17];
    const float* P2  = (const float*)d_in[18];
    const float* pb2 = (const float*)d_in[19];
    float* out = (float*)d_out;

    float *p_h1, *p_out1, *p_h2t, *p_h2, *p_z, *p_s1, *p_d1, *p_s2, *p_d2;
    cudaGetSymbolAddress((void**)&p_h1,   g_h1);
    cudaGetSymbolAddress((void**)&p_out1, g_out1);
    cudaGetSymbolAddress((void**)&p_h2t,  g_h2t);
    cudaGetSymbolAddress((void**)&p_h2,   g_h2);
    cudaGetSymbolAddress((void**)&p_z,    g_z);
    cudaGetSymbolAddress((void**)&p_s1,   g_s1);
    cudaGetSymbolAddress((void**)&p_d1,   g_d1);
    cudaGetSymbolAddress((void**)&p_s2,   g_s2);
    cudaGetSymbolAddress((void**)&p_d2,   g_d2);

    zero_k<<<(NN + 255) / 256, 256>>>();
    wev_k<<<1, FE * HEADS + FE>>>(We1, ae1, We2, ae2);
    aeproj_k<<<(EE + 7) / 8, 256>>>(ea);
    hist_k<<<(E2 + 255) / 256, 256>>>(ei);
    scan_k<<<1, 1024>>>();
    fill_k<<<(E2 + 255) / 256, 256>>>(ei);

    // layer 1: GEMM with fused attention dots
    sgemm_k<<<dim3(D1 / 128, (NN + 127) / 128), 256>>>(NN, D1, FIN, x, W1, p_h1,
            nullptr, nullptr, 0, as1, ad1, p_s1, p_d1, HEADS);
    wcalc1_k<<<(NN + 7) / 8, 256>>>();
    agg1_k<<<NN, 128>>>(p_h1, b1, p_out1);

    // layer 2
    sgemm_k<<<dim3(1, (NN + 127) / 128), 256>>>(NN, HID, D1, p_out1, W2, p_h2t,
            nullptr, nullptr, 0, as2, ad2, p_s2, p_d2, 1);
    wcalc2_k<<<(NN + 7) / 8, 256>>>();
    agg2_k<<<(NN + 7) / 8, 256>>>(p_h2t, b2, p_h2);

    // projection head
    sgemm_k<<<dim3(1, (NN + 127) / 128), 256>>>(NN, HID, HID, p_h2, P1, p_z,
            pb1, pa, 2, nullptr, nullptr, nullptr, nullptr, 1);
    sgemm_k<<<dim3(1, (NN + 127) / 128), 256>>>(NN, HID, HID, p_z, P2, out,
            pb2, nullptr, 3, nullptr, nullptr, nullptr, nullptr, 1);

    // g = sigmoid(mean(h_proj, axis=0))
    colsum_k<<<128, 128>>>(out);
    final_k<<<1, 128>>>(out + (size_t)NN * HID);
}